// round 4
// baseline (speedup 1.0000x reference)
#include <cuda_runtime.h>
#include <cstdint>

#define B_  16
#define T_  4096
#define D_  512
#define C_  10
#define FW_ 100
#define KW_ 201   // 2*FW+1

// ---------------- scratch (device globals; no allocations allowed) ----------
__device__ float g_bias[B_ * D_];             // b_enc[d] + (query @ W_dec.T)[b,d]
__device__ float g_conv_pad[B_ * T_ * 32];    // [b*T+t][32]: cols 0..9 = conv, rest 0
__device__ float g_watt_pad[D_ * 32];         // [d][32]: cols 0..9 = W_att[d][c], rest 0
__device__ float g_epart[B_ * T_ * 4];        // partial e per d-tile
__device__ float g_ctxp[B_ * 8 * D_];         // context partials per t-segment

// ---------------- helpers ---------------------------------------------------
__device__ __forceinline__ unsigned f2tf(float x) {
    unsigned u;
    asm("cvt.rna.tf32.f32 %0, %1;" : "=r"(u) : "f"(x));
    return u;
}
__device__ __forceinline__ uint32_t smem_u32(const void* p) {
    uint32_t a;
    asm("{ .reg .u64 t; cvta.to.shared.u64 t, %1; cvt.u32.u64 %0, t; }" : "=r"(a) : "l"(p));
    return a;
}
__device__ __forceinline__ void cp16(uint32_t dst, const void* src) {
    asm volatile("cp.async.cg.shared.global [%0], [%1], 16;" :: "r"(dst), "l"(src));
}
__device__ __forceinline__ void cp_commit() {
    asm volatile("cp.async.commit_group;" ::: "memory");
}
template <int N>
__device__ __forceinline__ void cp_wait() {
    asm volatile("cp.async.wait_group %0;" :: "n"(N) : "memory");
}
__device__ __forceinline__ void ldsm_x4(unsigned& r0, unsigned& r1, unsigned& r2, unsigned& r3,
                                        uint32_t addr) {
    asm volatile("ldmatrix.sync.aligned.m8n8.x4.shared.b16 {%0,%1,%2,%3}, [%4];"
                 : "=r"(r0), "=r"(r1), "=r"(r2), "=r"(r3) : "r"(addr));
}
__device__ __forceinline__ void ldsm_x2(unsigned& r0, unsigned& r1, uint32_t addr) {
    asm volatile("ldmatrix.sync.aligned.m8n8.x2.shared.b16 {%0,%1}, [%2];"
                 : "=r"(r0), "=r"(r1) : "r"(addr));
}
__device__ __forceinline__ void mma8(float& c0, float& c1, float& c2, float& c3,
                                     unsigned a0, unsigned a1, unsigned a2, unsigned a3,
                                     unsigned b0, unsigned b1) {
    asm volatile(
        "mma.sync.aligned.m16n8k8.row.col.f32.tf32.tf32.f32 "
        "{%0,%1,%2,%3}, {%4,%5,%6,%7}, {%8,%9}, {%0,%1,%2,%3};"
        : "+f"(c0), "+f"(c1), "+f"(c2), "+f"(c3)
        : "r"(a0), "r"(a1), "r"(a2), "r"(a3), "r"(b0), "r"(b1));
}

// ---------------- kernel 1: bias + W_att padding ----------------------------
__global__ __launch_bounds__(256)
void bias_kernel(const float* __restrict__ query, const float* __restrict__ W_dec,
                 const float* __restrict__ b_enc, const float* __restrict__ W_att) {
    const int b = blockIdx.x;
    const int tid = threadIdx.x;
    #pragma unroll
    for (int j = 0; j < 4; j++) {
        int idx = tid + j * 256;          // 0..1023 -> rows b*32 .. b*32+31
        int r = b * 32 + (idx >> 5);
        int cc = idx & 31;
        g_watt_pad[r * 32 + cc] = (cc < C_) ? W_att[r * C_ + cc] : 0.f;
    }
    __shared__ float qS[D_];
    qS[tid]       = query[b * D_ + tid];
    qS[tid + 256] = query[b * D_ + tid + 256];
    __syncthreads();
    const int warp = tid >> 5, lane = tid & 31;
    for (int r = warp; r < D_; r += 8) {
        float s = 0.f;
        const float* wp = W_dec + (size_t)r * D_;
        for (int k = lane; k < D_; k += 32) s += wp[k] * qS[k];
        #pragma unroll
        for (int o = 16; o > 0; o >>= 1) s += __shfl_xor_sync(0xffffffffu, s, o);
        if (lane == 0) g_bias[b * D_ + r] = s + b_enc[r];
    }
}

// ---------------- kernel 2: conv -> padded [b*T+t][32] layout ---------------
__global__ __launch_bounds__(256)
void conv_kernel(const float* __restrict__ att_prev, const float* __restrict__ W_conv) {
    const int b  = blockIdx.y;
    const int t0 = blockIdx.x * 256;
    __shared__ float ap[256 + 2 * FW_];
    __shared__ float wS[C_ * KW_];
    const int tid = threadIdx.x;
    for (int i = tid; i < C_ * KW_; i += 256) wS[i] = W_conv[i];
    for (int i = tid; i < 256 + 2 * FW_; i += 256) {
        int t = t0 + i - FW_;
        ap[i] = (t >= 0 && t < T_) ? att_prev[(size_t)b * T_ + t] : 0.f;
    }
    __syncthreads();
    float acc[C_];
    #pragma unroll
    for (int cc = 0; cc < C_; cc++) acc[cc] = 0.f;
    for (int k = 0; k < KW_; k++) {
        float a = ap[tid + k];
        #pragma unroll
        for (int cc = 0; cc < C_; cc++) acc[cc] += a * wS[cc * KW_ + k];
    }
    float* dst = &g_conv_pad[((size_t)b * T_ + t0 + tid) * 32];
    #pragma unroll
    for (int cc = 0; cc < C_; cc++) dst[cc] = acc[cc];
    #pragma unroll
    for (int cc = C_; cc < 32; cc++) dst[cc] = 0.f;
}

// ---------------- kernel 3: pipelined TF32 mma.sync GEMM + e epilogue -------
// Tile per CTA: 128 tokens x 128 d, K = 544 (17 k-tiles of 32).
// 2-stage cp.async double buffer (raw f32), ldmatrix fragments, cvt post-load.
#define ROWPITCH 144                     // 36 f32 per row (pad for banks)
#define A_BYTES  (128 * ROWPITCH)        // 18432
#define ST_BYTES (2 * A_BYTES)           // A + B per stage = 36864
#define DYN_SMEM (2 * ST_BYTES)          // 73728

__device__ __forceinline__ void stage_cp(const float* __restrict__ srcA, int ldA,
                                         const float* __restrict__ srcB, int ldB,
                                         uint32_t sA, uint32_t sB, int tid) {
    #pragma unroll
    for (int i = 0; i < 4; i++) {
        int slot = tid + i * 256;         // 1024 slots = 128 rows x 8 x 16B
        int r = slot >> 3, c4 = slot & 7;
        cp16(sA + r * ROWPITCH + c4 * 16, srcA + (size_t)r * ldA + c4 * 4);
    }
    #pragma unroll
    for (int i = 0; i < 4; i++) {
        int slot = tid + i * 256;
        int r = slot >> 3, c4 = slot & 7;
        cp16(sB + r * ROWPITCH + c4 * 16, srcB + (size_t)r * ldB + c4 * 4);
    }
}

__global__ __launch_bounds__(256, 2)
void gemm_e_kernel(const float* __restrict__ value, const float* __restrict__ W_enc,
                   const float* __restrict__ w_g) {
    extern __shared__ char dynsmem[];
    const uint32_t sb = smem_u32(dynsmem);

    __shared__ float biasS[128];
    __shared__ float wgS[128];
    __shared__ float redS[128][4];

    const int tid  = threadIdx.x;
    const int lane = tid & 31;
    const int warp = tid >> 5;
    const int wm = warp >> 2;            // 0..1
    const int wn = warp & 3;             // 0..3
    const int q  = lane & 3;
    const int g  = lane >> 2;

    const int b  = blockIdx.z;
    const int t0 = blockIdx.x * 128;
    const int d0 = blockIdx.y * 128;
    const size_t tok0 = (size_t)b * T_ + t0;

    if (tid < 128) {
        biasS[tid] = g_bias[b * D_ + d0 + tid];
        wgS[tid]   = w_g[d0 + tid];
    }

    float c[4][4][4];
    #pragma unroll
    for (int mi = 0; mi < 4; mi++)
        #pragma unroll
        for (int ni = 0; ni < 4; ni++)
            #pragma unroll
            for (int e = 0; e < 4; e++) c[mi][ni][e] = 0.f;

    const float* Ag = value + tok0 * D_;
    const float* Bg = W_enc + (size_t)d0 * D_;

    // prologue: stage tile 0
    stage_cp(Ag, D_, Bg, D_, sb, sb + A_BYTES, tid);
    cp_commit();

    // per-lane ldmatrix base addresses (within a stage)
    const uint32_t aOff = (uint32_t)((wm * 64 + (lane & 15)) * ROWPITCH + ((lane >> 4) << 4));
    const uint32_t bOff = (uint32_t)((wn * 32 + (lane & 7)) * ROWPITCH + ((lane & 8) << 1));

    for (int kt = 0; kt < 17; kt++) {
        const int s = kt & 1;
        if (kt < 16) {
            const int j = kt + 1;
            const uint32_t sA = sb + (j & 1) * ST_BYTES;
            if (j < 16) {
                stage_cp(Ag + j * 32, D_, Bg + j * 32, D_, sA, sA + A_BYTES, tid);
            } else {
                stage_cp(g_conv_pad + tok0 * 32, 32,
                         g_watt_pad + (size_t)d0 * 32, 32, sA, sA + A_BYTES, tid);
            }
            cp_commit();
            cp_wait<1>();
        } else {
            cp_wait<0>();
        }
        __syncthreads();

        const uint32_t aBase = sb + s * ST_BYTES + aOff;
        const uint32_t bBase = sb + s * ST_BYTES + A_BYTES + bOff;
        #pragma unroll
        for (int k8 = 0; k8 < 4; k8++) {
            unsigned af[4][4], bf[4][2];
            #pragma unroll
            for (int mi = 0; mi < 4; mi++)
                ldsm_x4(af[mi][0], af[mi][1], af[mi][2], af[mi][3],
                        aBase + mi * (16 * ROWPITCH) + k8 * 32);
            #pragma unroll
            for (int ni = 0; ni < 4; ni++)
                ldsm_x2(bf[ni][0], bf[ni][1],
                        bBase + ni * (8 * ROWPITCH) + k8 * 32);
            #pragma unroll
            for (int mi = 0; mi < 4; mi++)
                #pragma unroll
                for (int j = 0; j < 4; j++)
                    af[mi][j] = f2tf(__uint_as_float(af[mi][j]));
            #pragma unroll
            for (int ni = 0; ni < 4; ni++) {
                bf[ni][0] = f2tf(__uint_as_float(bf[ni][0]));
                bf[ni][1] = f2tf(__uint_as_float(bf[ni][1]));
            }
            #pragma unroll
            for (int mi = 0; mi < 4; mi++)
                #pragma unroll
                for (int ni = 0; ni < 4; ni++)
                    mma8(c[mi][ni][0], c[mi][ni][1], c[mi][ni][2], c[mi][ni][3],
                         af[mi][0], af[mi][1], af[mi][2], af[mi][3],
                         bf[ni][0], bf[ni][1]);
        }
        __syncthreads();
    }

    // epilogue: tanh + w_g dot, reduce over this block's 128 d columns
    float rs[4][2];
    #pragma unroll
    for (int mi = 0; mi < 4; mi++) { rs[mi][0] = 0.f; rs[mi][1] = 0.f; }
    #pragma unroll
    for (int mi = 0; mi < 4; mi++)
        #pragma unroll
        for (int ni = 0; ni < 4; ni++)
            #pragma unroll
            for (int e = 0; e < 4; e++) {
                int dl  = wn * 32 + ni * 8 + q * 2 + (e & 1);
                float x = c[mi][ni][e] + biasS[dl];
                rs[mi][e >> 1] += wgS[dl] * tanhf(x);
            }
    #pragma unroll
    for (int mi = 0; mi < 4; mi++)
        #pragma unroll
        for (int h = 0; h < 2; h++) {
            float v = rs[mi][h];
            v += __shfl_xor_sync(0xffffffffu, v, 1);
            v += __shfl_xor_sync(0xffffffffu, v, 2);
            if (q == 0) redS[wm * 64 + mi * 16 + h * 8 + g][wn] = v;
        }
    __syncthreads();
    if (tid < 128) {
        float ev = redS[tid][0] + redS[tid][1] + redS[tid][2] + redS[tid][3];
        g_epart[(tok0 + tid) * 4 + blockIdx.y] = ev;
    }
}

// ---------------- kernel 4: masked, sharpened softmax over T ----------------
__global__ __launch_bounds__(1024)
void softmax_kernel(const int* __restrict__ lens, float* __restrict__ out) {
    const int b   = blockIdx.x;
    const int len = lens[b];
    const int tid = threadIdx.x;
    __shared__ float sm[32];
    __shared__ float bc;

    float ev[4];
    float m = -1e30f;
    #pragma unroll
    for (int i = 0; i < 4; i++) {
        int t = tid + i * 1024;
        const float* p = &g_epart[((size_t)b * T_ + t) * 4];
        float e = p[0] + p[1] + p[2] + p[3];
        ev[i] = e;
        if (t < len) m = fmaxf(m, e);
    }
    #pragma unroll
    for (int o = 16; o > 0; o >>= 1) m = fmaxf(m, __shfl_xor_sync(0xffffffffu, m, o));
    if ((tid & 31) == 0) sm[tid >> 5] = m;
    __syncthreads();
    if (tid < 32) {
        float v = sm[tid];
        #pragma unroll
        for (int o = 16; o > 0; o >>= 1) v = fmaxf(v, __shfl_xor_sync(0xffffffffu, v, o));
        if (tid == 0) bc = v;
    }
    __syncthreads();
    const float M = bc;

    float s = 0.f;
    #pragma unroll
    for (int i = 0; i < 4; i++) {
        int t = tid + i * 1024;
        float w = (t < len) ? expf(2.0f * (ev[i] - M)) : 0.f;
        ev[i] = w;
        s += w;
    }
    #pragma unroll
    for (int o = 16; o > 0; o >>= 1) s += __shfl_xor_sync(0xffffffffu, s, o);
    __syncthreads();
    if ((tid & 31) == 0) sm[tid >> 5] = s;
    __syncthreads();
    if (tid < 32) {
        float v = sm[tid];
        #pragma unroll
        for (int o = 16; o > 0; o >>= 1) v += __shfl_xor_sync(0xffffffffu, v, o);
        if (tid == 0) bc = v;
    }
    __syncthreads();
    const float inv = 1.f / bc;
    #pragma unroll
    for (int i = 0; i < 4; i++) {
        int t = tid + i * 1024;
        out[B_ * D_ + (size_t)b * T_ + t] = ev[i] * inv;
    }
}

// ---------------- kernel 5: context partials over 8 t-segments --------------
__global__ __launch_bounds__(256)
void ctx_part_kernel(const float* __restrict__ value, const float* __restrict__ wts) {
    const int dch = blockIdx.x, seg = blockIdx.y, b = blockIdx.z;
    __shared__ float wS[512];
    const int tid = threadIdx.x;
    const int t0  = seg * 512;
    wS[tid]       = wts[(size_t)b * T_ + t0 + tid];
    wS[tid + 256] = wts[(size_t)b * T_ + t0 + tid + 256];
    __syncthreads();
    const int d = dch * 256 + tid;
    const float* vp = value + ((size_t)b * T_ + t0) * D_ + d;
    float acc = 0.f;
    #pragma unroll 8
    for (int t = 0; t < 512; t++) acc += vp[(size_t)t * D_] * wS[t];
    g_ctxp[((size_t)(b * 8 + seg)) * D_ + d] = acc;
}

// ---------------- kernel 6: context reduce ----------------------------------
__global__ __launch_bounds__(512)
void ctx_reduce_kernel(float* __restrict__ out) {
    const int b = blockIdx.x;
    const int d = threadIdx.x;
    float s = 0.f;
    #pragma unroll
    for (int seg = 0; seg < 8; seg++) s += g_ctxp[((size_t)(b * 8 + seg)) * D_ + d];
    out[b * D_ + d] = s;
}

// ---------------- launch -----------------------------------------------------
extern "C" void kernel_launch(void* const* d_in, const int* in_sizes, int n_in,
                              void* d_out, int out_size) {
    const float* value   = (const float*)d_in[0];
    const float* query   = (const float*)d_in[1];
    const int*   lens    = (const int*)  d_in[2];
    const float* attprev = (const float*)d_in[3];
    const float* W_enc   = (const float*)d_in[4];
    const float* b_enc   = (const float*)d_in[5];
    const float* W_dec   = (const float*)d_in[6];
    const float* W_att   = (const float*)d_in[7];
    const float* W_conv  = (const float*)d_in[8];
    const float* w_g     = (const float*)d_in[9];
    // d_in[10] = b_g: constant shift, cancels under softmax -> unused
    float* out = (float*)d_out;   // [0,8192) = context, [8192,73728) = att_weights

    // idempotent + deterministic; called every time (no static guards)
    cudaFuncSetAttribute(gemm_e_kernel,
                         cudaFuncAttributeMaxDynamicSharedMemorySize, DYN_SMEM);

    bias_kernel<<<B_, 256>>>(query, W_dec, b_enc, W_att);
    conv_kernel<<<dim3(T_ / 256, B_), 256>>>(attprev, W_conv);
    gemm_e_kernel<<<dim3(T_ / 128, 4, B_), 256, DYN_SMEM>>>(value, W_enc, w_g);
    softmax_kernel<<<B_, 1024>>>(lens, out);
    ctx_part_kernel<<<dim3(2, 8, B_), 256>>>(value, out + B_ * D_);
    ctx_reduce_kernel<<<B_, 512>>>(out);
}

// round 6
// speedup vs baseline: 1.6458x; 1.6458x over previous
#include <cuda_runtime.h>
#include <cstdint>

#define B_  16
#define T_  4096
#define D_  512
#define C_  10
#define FW_ 100
#define KW_ 201   // 2*FW+1

// ---------------- scratch (device globals; no allocations allowed) ----------
__device__ float g_bias[B_ * D_];             // b_enc[d] + (query @ W_dec.T)[b,d]
__device__ float g_wenc_tf[D_ * D_];          // W_enc pre-rounded to tf32
__device__ float g_conv_pad[B_ * T_ * 32];    // [b*T+t][32]: cols 0..9 conv (tf32-rounded)
__device__ float g_watt_pad[D_ * 32];         // [d][32]: cols 0..9 W_att (tf32-rounded)
__device__ float g_epart[B_ * T_ * 2];        // partial e per d-half
__device__ float g_ctxp[B_ * 8 * D_];         // context partials per t-segment

// ---------------- helpers ---------------------------------------------------
__device__ __forceinline__ float f2tf_f(float x) {
    unsigned u;
    asm("cvt.rna.tf32.f32 %0, %1;" : "=r"(u) : "f"(x));
    return __uint_as_float(u);
}
__device__ __forceinline__ uint32_t smem_u32(const void* p) {
    uint32_t a;
    asm("{ .reg .u64 t; cvta.to.shared.u64 t, %1; cvt.u32.u64 %0, t; }" : "=r"(a) : "l"(p));
    return a;
}
__device__ __forceinline__ void cp16(uint32_t dst, const void* src) {
    asm volatile("cp.async.cg.shared.global [%0], [%1], 16;" :: "r"(dst), "l"(src));
}
__device__ __forceinline__ void cp_commit() {
    asm volatile("cp.async.commit_group;" ::: "memory");
}
template <int N>
__device__ __forceinline__ void cp_wait() {
    asm volatile("cp.async.wait_group %0;" :: "n"(N) : "memory");
}
__device__ __forceinline__ void ldsm_x4(unsigned& r0, unsigned& r1, unsigned& r2, unsigned& r3,
                                        uint32_t addr) {
    asm volatile("ldmatrix.sync.aligned.m8n8.x4.shared.b16 {%0,%1,%2,%3}, [%4];"
                 : "=r"(r0), "=r"(r1), "=r"(r2), "=r"(r3) : "r"(addr));
}
__device__ __forceinline__ void mma8(float& c0, float& c1, float& c2, float& c3,
                                     unsigned a0, unsigned a1, unsigned a2, unsigned a3,
                                     unsigned b0, unsigned b1) {
    asm volatile(
        "mma.sync.aligned.m16n8k8.row.col.f32.tf32.tf32.f32 "
        "{%0,%1,%2,%3}, {%4,%5,%6,%7}, {%8,%9}, {%0,%1,%2,%3};"
        : "+f"(c0), "+f"(c1), "+f"(c2), "+f"(c3)
        : "r"(a0), "r"(a1), "r"(a2), "r"(a3), "r"(b0), "r"(b1));
}

// ---------------- kernel 1: bias + W_att pad + W_enc tf32 pre-round ---------
__global__ __launch_bounds__(256)
void bias_kernel(const float* __restrict__ query, const float* __restrict__ W_dec,
                 const float* __restrict__ b_enc, const float* __restrict__ W_att,
                 const float* __restrict__ W_enc) {
    const int b = blockIdx.x;
    const int tid = threadIdx.x;
    // pre-round this block's 1/16 slice of W_enc
    {
        const int base = b * (D_ * D_ / B_);
        #pragma unroll 4
        for (int i = tid; i < D_ * D_ / B_; i += 256)
            g_wenc_tf[base + i] = f2tf_f(W_enc[base + i]);
    }
    // pad + round W_att rows [b*32, b*32+32)
    #pragma unroll
    for (int j = 0; j < 4; j++) {
        int idx = tid + j * 256;
        int r = b * 32 + (idx >> 5);
        int cc = idx & 31;
        g_watt_pad[r * 32 + cc] = (cc < C_) ? f2tf_f(W_att[r * C_ + cc]) : 0.f;
    }
    __shared__ float qS[D_];
    qS[tid]       = query[b * D_ + tid];
    qS[tid + 256] = query[b * D_ + tid + 256];
    __syncthreads();
    const int warp = tid >> 5, lane = tid & 31;
    for (int r = warp; r < D_; r += 8) {
        float s = 0.f;
        const float* wp = W_dec + (size_t)r * D_;
        for (int k = lane; k < D_; k += 32) s += wp[k] * qS[k];
        #pragma unroll
        for (int o = 16; o > 0; o >>= 1) s += __shfl_xor_sync(0xffffffffu, s, o);
        if (lane == 0) g_bias[b * D_ + r] = s + b_enc[r];
    }
}

// ---------------- kernel 2: conv -> padded + tf32-rounded -------------------
__global__ __launch_bounds__(256)
void conv_kernel(const float* __restrict__ att_prev, const float* __restrict__ W_conv) {
    const int b  = blockIdx.y;
    const int t0 = blockIdx.x * 256;
    __shared__ float ap[256 + 2 * FW_];
    __shared__ float wS[C_ * KW_];
    const int tid = threadIdx.x;
    for (int i = tid; i < C_ * KW_; i += 256) wS[i] = W_conv[i];
    for (int i = tid; i < 256 + 2 * FW_; i += 256) {
        int t = t0 + i - FW_;
        ap[i] = (t >= 0 && t < T_) ? att_prev[(size_t)b * T_ + t] : 0.f;
    }
    __syncthreads();
    float acc[C_];
    #pragma unroll
    for (int cc = 0; cc < C_; cc++) acc[cc] = 0.f;
    for (int k = 0; k < KW_; k++) {
        float a = ap[tid + k];
        #pragma unroll
        for (int cc = 0; cc < C_; cc++) acc[cc] += a * wS[cc * KW_ + k];
    }
    float* dst = &g_conv_pad[((size_t)b * T_ + t0 + tid) * 32];
    #pragma unroll
    for (int cc = 0; cc < C_; cc++) dst[cc] = f2tf_f(acc[cc]);
    #pragma unroll
    for (int cc = C_; cc < 32; cc++) dst[cc] = 0.f;
}

// ---------------- kernel 3: pipelined TF32 GEMM + e epilogue ----------------
// Tile per CTA: 128 tokens x 256 d, K = 544 (17 k-tiles of 32), 512 threads.
// 3-stage cp.async; raw f32 bits fed to mma.tf32 (A truncated, B pre-rounded).
#define ROWPITCH 144
#define A_BYTES  (128 * ROWPITCH)        // 18432
#define Bb_BYTES (256 * ROWPITCH)        // 36864
#define ST_BYTES (A_BYTES + Bb_BYTES)    // 55296
#define NSTAGE   3
#define DYN_SMEM (NSTAGE * ST_BYTES)     // 165888

__device__ __forceinline__ void stage_cp(const float* __restrict__ srcA, int ldA,
                                         const float* __restrict__ srcB, int ldB,
                                         uint32_t st, int tid) {
    #pragma unroll
    for (int i = 0; i < 2; i++) {
        int slot = tid + i * 512;            // 1024 slots: 128 rows x 8 x 16B
        int r = slot >> 3, c4 = slot & 7;
        cp16(st + r * ROWPITCH + c4 * 16, srcA + (size_t)r * ldA + c4 * 4);
    }
    #pragma unroll
    for (int i = 0; i < 4; i++) {
        int slot = tid + i * 512;            // 2048 slots: 256 rows x 8 x 16B
        int r = slot >> 3, c4 = slot & 7;
        cp16(st + A_BYTES + r * ROWPITCH + c4 * 16, srcB + (size_t)r * ldB + c4 * 4);
    }
}

__global__ __launch_bounds__(512, 1)
void gemm_e_kernel(const float* __restrict__ value, const float* __restrict__ w_g) {
    extern __shared__ char dynsmem[];
    const uint32_t sb = smem_u32(dynsmem);

    __shared__ float biasS[256];
    __shared__ float wgS[256];
    __shared__ float redS[128][4];

    const int tid  = threadIdx.x;
    const int lane = tid & 31;
    const int warp = tid >> 5;
    const int wm = warp & 3;             // row block (32 rows)
    const int wn = warp >> 2;            // col block (64 cols)
    const int q  = lane & 3;
    const int g  = lane >> 2;

    const int b  = blockIdx.z;
    const int t0 = blockIdx.x * 128;
    const int d0 = blockIdx.y * 256;
    const size_t tok0 = (size_t)b * T_ + t0;

    if (tid < 256) {
        biasS[tid] = g_bias[b * D_ + d0 + tid];
        wgS[tid]   = w_g[d0 + tid];
    }

    float c[2][8][4];
    #pragma unroll
    for (int mi = 0; mi < 2; mi++)
        #pragma unroll
        for (int ni = 0; ni < 8; ni++)
            #pragma unroll
            for (int e = 0; e < 4; e++) c[mi][ni][e] = 0.f;

    const float* Ag = value + tok0 * D_;
    const float* Bg = g_wenc_tf + (size_t)d0 * D_;

    // prologue: stage tiles 0 and 1
    stage_cp(Ag, D_, Bg, D_, sb, tid);
    cp_commit();
    stage_cp(Ag + 32, D_, Bg + 32, D_, sb + ST_BYTES, tid);
    cp_commit();

    // per-lane ldmatrix offsets (within a stage)
    const uint32_t aOff = (uint32_t)((wm * 32 + (lane & 15)) * ROWPITCH + ((lane >> 4) << 4));
    const uint32_t bOff = (uint32_t)((wn * 64 + (lane & 7) + (((lane >> 4) & 1) << 3)) * ROWPITCH
                                     + (((lane >> 3) & 1) << 4));

    for (int kt = 0; kt < 17; kt++) {
        const int j = kt + 2;
        if (j <= 16) {
            const uint32_t st = sb + (j % NSTAGE) * ST_BYTES;
            if (j < 16)
                stage_cp(Ag + j * 32, D_, Bg + j * 32, D_, st, tid);
            else
                stage_cp(g_conv_pad + tok0 * 32, 32,
                         g_watt_pad + (size_t)d0 * 32, 32, st, tid);
        }
        cp_commit();
        cp_wait<2>();
        __syncthreads();

        const uint32_t stage = sb + (kt % NSTAGE) * ST_BYTES;
        const uint32_t aBase = stage + aOff;
        const uint32_t bBase = stage + A_BYTES + bOff;
        #pragma unroll
        for (int k8 = 0; k8 < 4; k8++) {
            unsigned af[2][4], bf[8][2];
            #pragma unroll
            for (int mi = 0; mi < 2; mi++)
                ldsm_x4(af[mi][0], af[mi][1], af[mi][2], af[mi][3],
                        aBase + mi * (16 * ROWPITCH) + k8 * 32);
            #pragma unroll
            for (int p = 0; p < 4; p++)
                ldsm_x4(bf[2 * p][0], bf[2 * p][1], bf[2 * p + 1][0], bf[2 * p + 1][1],
                        bBase + p * (16 * ROWPITCH) + k8 * 32);
            #pragma unroll
            for (int mi = 0; mi < 2; mi++)
                #pragma unroll
                for (int ni = 0; ni < 8; ni++)
                    mma8(c[mi][ni][0], c[mi][ni][1], c[mi][ni][2], c[mi][ni][3],
                         af[mi][0], af[mi][1], af[mi][2], af[mi][3],
                         bf[ni][0], bf[ni][1]);
        }
        __syncthreads();
    }

    // epilogue: tanh + w_g dot, reduce over this block's 256 d columns
    float rs[2][2];
    rs[0][0] = rs[0][1] = rs[1][0] = rs[1][1] = 0.f;
    #pragma unroll
    for (int mi = 0; mi < 2; mi++)
        #pragma unroll
        for (int ni = 0; ni < 8; ni++)
            #pragma unroll
            for (int e = 0; e < 4; e++) {
                int dl  = wn * 64 + ni * 8 + q * 2 + (e & 1);
                float x = c[mi][ni][e] + biasS[dl];
                rs[mi][e >> 1] += wgS[dl] * tanhf(x);
            }
    #pragma unroll
    for (int mi = 0; mi < 2; mi++)
        #pragma unroll
        for (int h = 0; h < 2; h++) {
            float v = rs[mi][h];
            v += __shfl_xor_sync(0xffffffffu, v, 1);
            v += __shfl_xor_sync(0xffffffffu, v, 2);
            if (q == 0) redS[wm * 32 + mi * 16 + h * 8 + g][wn] = v;
        }
    __syncthreads();
    if (tid < 128) {
        float ev = redS[tid][0] + redS[tid][1] + redS[tid][2] + redS[tid][3];
        g_epart[(tok0 + tid) * 2 + blockIdx.y] = ev;
    }
}

// ---------------- kernel 4: masked, sharpened softmax over T ----------------
__global__ __launch_bounds__(1024)
void softmax_kernel(const int* __restrict__ lens, float* __restrict__ out) {
    const int b   = blockIdx.x;
    const int len = lens[b];
    const int tid = threadIdx.x;
    __shared__ float sm[32];
    __shared__ float bc;

    float ev[4];
    float m = -1e30f;
    #pragma unroll
    for (int i = 0; i < 4; i++) {
        int t = tid + i * 1024;
        const float* p = &g_epart[((size_t)b * T_ + t) * 2];
        float e = p[0] + p[1];
        ev[i] = e;
        if (t < len) m = fmaxf(m, e);
    }
    #pragma unroll
    for (int o = 16; o > 0; o >>= 1) m = fmaxf(m, __shfl_xor_sync(0xffffffffu, m, o));
    if ((tid & 31) == 0) sm[tid >> 5] = m;
    __syncthreads();
    if (tid < 32) {
        float v = sm[tid];
        #pragma unroll
        for (int o = 16; o > 0; o >>= 1) v = fmaxf(v, __shfl_xor_sync(0xffffffffu, v, o));
        if (tid == 0) bc = v;
    }
    __syncthreads();
    const float M = bc;

    float s = 0.f;
    #pragma unroll
    for (int i = 0; i < 4; i++) {
        int t = tid + i * 1024;
        float w = (t < len) ? expf(2.0f * (ev[i] - M)) : 0.f;
        ev[i] = w;
        s += w;
    }
    #pragma unroll
    for (int o = 16; o > 0; o >>= 1) s += __shfl_xor_sync(0xffffffffu, s, o);
    __syncthreads();
    if ((tid & 31) == 0) sm[tid >> 5] = s;
    __syncthreads();
    if (tid < 32) {
        float v = sm[tid];
        #pragma unroll
        for (int o = 16; o > 0; o >>= 1) v += __shfl_xor_sync(0xffffffffu, v, o);
        if (tid == 0) bc = v;
    }
    __syncthreads();
    const float inv = 1.f / bc;
    #pragma unroll
    for (int i = 0; i < 4; i++) {
        int t = tid + i * 1024;
        out[B_ * D_ + (size_t)b * T_ + t] = ev[i] * inv;
    }
}

// ---------------- kernel 5: context partials over 8 t-segments --------------
__global__ __launch_bounds__(256)
void ctx_part_kernel(const float* __restrict__ value, const float* __restrict__ wts) {
    const int dch = blockIdx.x, seg = blockIdx.y, b = blockIdx.z;
    __shared__ float wS[512];
    const int tid = threadIdx.x;
    const int t0  = seg * 512;
    wS[tid]       = wts[(size_t)b * T_ + t0 + tid];
    wS[tid + 256] = wts[(size_t)b * T_ + t0 + tid + 256];
    __syncthreads();
    const int d = dch * 256 + tid;
    const float* vp = value + ((size_t)b * T_ + t0) * D_ + d;
    float acc = 0.f;
    #pragma unroll 8
    for (int t = 0; t < 512; t++) acc += vp[(size_t)t * D_] * wS[t];
    g_ctxp[((size_t)(b * 8 + seg)) * D_ + d] = acc;
}

// ---------------- kernel 6: context reduce ----------------------------------
__global__ __launch_bounds__(512)
void ctx_reduce_kernel(float* __restrict__ out) {
    const int b = blockIdx.x;
    const int d = threadIdx.x;
    float s = 0.f;
    #pragma unroll
    for (int seg = 0; seg < 8; seg++) s += g_ctxp[((size_t)(b * 8 + seg)) * D_ + d];
    out[b * D_ + d] = s;
}

// ---------------- launch -----------------------------------------------------
extern "C" void kernel_launch(void* const* d_in, const int* in_sizes, int n_in,
                              void* d_out, int out_size) {
    const float* value   = (const float*)d_in[0];
    const float* query   = (const float*)d_in[1];
    const int*   lens    = (const int*)  d_in[2];
    const float* attprev = (const float*)d_in[3];
    const float* W_enc   = (const float*)d_in[4];
    const float* b_enc   = (const float*)d_in[5];
    const float* W_dec   = (const float*)d_in[6];
    const float* W_att   = (const float*)d_in[7];
    const float* W_conv  = (const float*)d_in[8];
    const float* w_g     = (const float*)d_in[9];
    // d_in[10] = b_g: constant shift, cancels under softmax -> unused
    float* out = (float*)d_out;   // [0,8192) = context, [8192,73728) = att_weights

    cudaFuncSetAttribute(gemm_e_kernel,
                         cudaFuncAttributeMaxDynamicSharedMemorySize, DYN_SMEM);

    bias_kernel<<<B_, 256>>>(query, W_dec, b_enc, W_att, W_enc);
    conv_kernel<<<dim3(T_ / 256, B_), 256>>>(attprev, W_conv);
    gemm_e_kernel<<<dim3(T_ / 128, 2, B_), 512, DYN_SMEM>>>(value, w_g);
    softmax_kernel<<<B_, 1024>>>(lens, out);
    ctx_part_kernel<<<dim3(2, 8, B_), 256>>>(value, out + B_ * D_);
    ctx_reduce_kernel<<<B_, 512>>>(out);
}

// round 7
// speedup vs baseline: 1.8721x; 1.1375x over previous
#include <cuda_runtime.h>
#include <cuda_fp16.h>
#include <cstdint>

#define B_  16
#define T_  4096
#define D_  512
#define C_  10
#define FW_ 100
#define KW_ 201   // 2*FW+1

// ---------------- scratch (device globals; no allocations allowed) ----------
__device__ float  g_bias[B_ * D_];            // b_enc[d] + (query @ W_dec.T)[b,d]
__device__ __half g_val_h[(size_t)B_ * T_ * D_];   // value in fp16 (64 MB)
__device__ __half g_wenc_h[D_ * D_];          // W_enc fp16 [d][k]
__device__ __half g_conv_h[(size_t)B_ * T_ * 32];  // [b*T+t][32]: 0..9 conv, rest 0
__device__ __half g_watt_h[D_ * 32];          // [d][32]: 0..9 W_att, rest 0
__device__ float  g_epart[B_ * T_ * 2];       // partial e per d-half
__device__ float  g_ctxp[B_ * 8 * D_];        // context partials per t-segment

// ---------------- helpers ---------------------------------------------------
__device__ __forceinline__ uint32_t smem_u32(const void* p) {
    uint32_t a;
    asm("{ .reg .u64 t; cvta.to.shared.u64 t, %1; cvt.u32.u64 %0, t; }" : "=r"(a) : "l"(p));
    return a;
}
__device__ __forceinline__ void cp16(uint32_t dst, const void* src) {
    asm volatile("cp.async.cg.shared.global [%0], [%1], 16;" :: "r"(dst), "l"(src));
}
__device__ __forceinline__ void cp_commit() {
    asm volatile("cp.async.commit_group;" ::: "memory");
}
template <int N>
__device__ __forceinline__ void cp_wait() {
    asm volatile("cp.async.wait_group %0;" :: "n"(N) : "memory");
}
__device__ __forceinline__ void ldsm_x4(unsigned& r0, unsigned& r1, unsigned& r2, unsigned& r3,
                                        uint32_t addr) {
    asm volatile("ldmatrix.sync.aligned.m8n8.x4.shared.b16 {%0,%1,%2,%3}, [%4];"
                 : "=r"(r0), "=r"(r1), "=r"(r2), "=r"(r3) : "r"(addr));
}
__device__ __forceinline__ void mma16(float& c0, float& c1, float& c2, float& c3,
                                      unsigned a0, unsigned a1, unsigned a2, unsigned a3,
                                      unsigned b0, unsigned b1) {
    asm volatile(
        "mma.sync.aligned.m16n8k16.row.col.f32.f16.f16.f32 "
        "{%0,%1,%2,%3}, {%4,%5,%6,%7}, {%8,%9}, {%0,%1,%2,%3};"
        : "+f"(c0), "+f"(c1), "+f"(c2), "+f"(c3)
        : "r"(a0), "r"(a1), "r"(a2), "r"(a3), "r"(b0), "r"(b1));
}

// ---------------- kernel 0: value -> fp16 ------------------------------------
__global__ __launch_bounds__(256)
void cvt_value_kernel(const float* __restrict__ v) {
    const size_t i = ((size_t)blockIdx.x * 256 + threadIdx.x) * 4;
    float4 f = *reinterpret_cast<const float4*>(v + i);
    __half2* dst = reinterpret_cast<__half2*>(g_val_h + i);
    dst[0] = __floats2half2_rn(f.x, f.y);
    dst[1] = __floats2half2_rn(f.z, f.w);
}

// ---------------- kernel 1: bias + W_att pad + W_enc fp16 -------------------
__global__ __launch_bounds__(256)
void bias_kernel(const float* __restrict__ query, const float* __restrict__ W_dec,
                 const float* __restrict__ b_enc, const float* __restrict__ W_att,
                 const float* __restrict__ W_enc) {
    const int b = blockIdx.x;
    const int tid = threadIdx.x;
    {
        const int base = b * (D_ * D_ / B_);
        #pragma unroll 4
        for (int i = tid; i < D_ * D_ / B_; i += 256)
            g_wenc_h[base + i] = __float2half_rn(W_enc[base + i]);
    }
    #pragma unroll
    for (int j = 0; j < 4; j++) {
        int idx = tid + j * 256;
        int r = b * 32 + (idx >> 5);
        int cc = idx & 31;
        g_watt_h[r * 32 + cc] = (cc < C_) ? __float2half_rn(W_att[r * C_ + cc])
                                          : __float2half_rn(0.f);
    }
    __shared__ float qS[D_];
    qS[tid]       = query[b * D_ + tid];
    qS[tid + 256] = query[b * D_ + tid + 256];
    __syncthreads();
    const int warp = tid >> 5, lane = tid & 31;
    for (int r = warp; r < D_; r += 8) {
        float s = 0.f;
        const float* wp = W_dec + (size_t)r * D_;
        for (int k = lane; k < D_; k += 32) s += wp[k] * qS[k];
        #pragma unroll
        for (int o = 16; o > 0; o >>= 1) s += __shfl_xor_sync(0xffffffffu, s, o);
        if (lane == 0) g_bias[b * D_ + r] = s + b_enc[r];
    }
}

// ---------------- kernel 2: conv -> padded fp16 -----------------------------
__global__ __launch_bounds__(256)
void conv_kernel(const float* __restrict__ att_prev, const float* __restrict__ W_conv) {
    const int b  = blockIdx.y;
    const int t0 = blockIdx.x * 256;
    __shared__ float ap[256 + 2 * FW_];
    __shared__ float wS[C_ * KW_];
    const int tid = threadIdx.x;
    for (int i = tid; i < C_ * KW_; i += 256) wS[i] = W_conv[i];
    for (int i = tid; i < 256 + 2 * FW_; i += 256) {
        int t = t0 + i - FW_;
        ap[i] = (t >= 0 && t < T_) ? att_prev[(size_t)b * T_ + t] : 0.f;
    }
    __syncthreads();
    float acc[C_];
    #pragma unroll
    for (int cc = 0; cc < C_; cc++) acc[cc] = 0.f;
    for (int k = 0; k < KW_; k++) {
        float a = ap[tid + k];
        #pragma unroll
        for (int cc = 0; cc < C_; cc++) acc[cc] += a * wS[cc * KW_ + k];
    }
    __half* dst = &g_conv_h[((size_t)b * T_ + t0 + tid) * 32];
    #pragma unroll
    for (int cc = 0; cc < C_; cc++) dst[cc] = __float2half_rn(acc[cc]);
    #pragma unroll
    for (int cc = C_; cc < 32; cc++) dst[cc] = __float2half_rn(0.f);
}

// ---------------- kernel 3: pipelined FP16 GEMM + e epilogue ----------------
// Tile per CTA: 128 tokens x 256 d, K = 544 (17 k-tiles of 32), 512 threads.
// 4-stage cp.async double buffer; mma.m16n8k16.f16 with f32 accumulate.
#define PITCH  80                        // bytes/row: 64B data + 16B pad
#define A_BY   (128 * PITCH)             // 10240
#define Bb_BY  (256 * PITCH)             // 20480
#define ST_BY  (A_BY + Bb_BY)            // 30720
#define NSTAGE 4
#define DYN_SMEM (NSTAGE * ST_BY)        // 122880

__device__ __forceinline__ void stage_cp(const __half* __restrict__ srcA, int ldA,
                                         const __half* __restrict__ srcB, int ldB,
                                         uint32_t st, int tid) {
    {
        int r = tid >> 2, c4 = tid & 3;  // 512 slots: 128 rows x 4 x 16B
        cp16(st + r * PITCH + c4 * 16, srcA + (size_t)r * ldA + c4 * 8);
    }
    #pragma unroll
    for (int i = 0; i < 2; i++) {
        int slot = tid + i * 512;        // 1024 slots: 256 rows x 4 x 16B
        int r = slot >> 2, c4 = slot & 3;
        cp16(st + A_BY + r * PITCH + c4 * 16, srcB + (size_t)r * ldB + c4 * 8);
    }
}

__global__ __launch_bounds__(512, 1)
void gemm_e_kernel(const float* __restrict__ w_g) {
    extern __shared__ char dynsmem[];
    const uint32_t sb = smem_u32(dynsmem);

    __shared__ float biasS[256];
    __shared__ float wgS[256];
    __shared__ float redS[128][4];

    const int tid  = threadIdx.x;
    const int lane = tid & 31;
    const int warp = tid >> 5;
    const int wm = warp & 3;             // row block (32 rows)
    const int wn = warp >> 2;            // col block (64 cols)
    const int q  = lane & 3;
    const int g  = lane >> 2;

    const int b  = blockIdx.z;
    const int t0 = blockIdx.x * 128;
    const int d0 = blockIdx.y * 256;
    const size_t tok0 = (size_t)b * T_ + t0;

    if (tid < 256) {
        biasS[tid] = g_bias[b * D_ + d0 + tid];
        wgS[tid]   = w_g[d0 + tid];
    }

    float c[2][8][4];
    #pragma unroll
    for (int mi = 0; mi < 2; mi++)
        #pragma unroll
        for (int ni = 0; ni < 8; ni++)
            #pragma unroll
            for (int e = 0; e < 4; e++) c[mi][ni][e] = 0.f;

    const __half* Ag = g_val_h + tok0 * D_;
    const __half* Bg = g_wenc_h + (size_t)d0 * D_;

    // prologue: stage tiles 0..2
    stage_cp(Ag,      D_, Bg,      D_, sb,             tid); cp_commit();
    stage_cp(Ag + 32, D_, Bg + 32, D_, sb + ST_BY,     tid); cp_commit();
    stage_cp(Ag + 64, D_, Bg + 64, D_, sb + 2 * ST_BY, tid); cp_commit();

    // per-lane ldmatrix offsets (within a stage)
    const uint32_t aOff = (uint32_t)((wm * 32 + (lane & 15)) * PITCH + ((lane >> 4) << 4));
    const uint32_t bOff = (uint32_t)((wn * 64 + (lane & 7) + (((lane >> 4) & 1) << 3)) * PITCH
                                     + (((lane >> 3) & 1) << 4));

    for (int kt = 0; kt < 17; kt++) {
        const int j = kt + 3;
        if (j <= 16) {
            const uint32_t st = sb + (j % NSTAGE) * ST_BY;
            if (j < 16)
                stage_cp(Ag + j * 32, D_, Bg + j * 32, D_, st, tid);
            else
                stage_cp(g_conv_h + tok0 * 32, 32,
                         g_watt_h + (size_t)d0 * 32, 32, st, tid);
        }
        cp_commit();
        cp_wait<3>();
        __syncthreads();

        const uint32_t stage = sb + (kt % NSTAGE) * ST_BY;
        const uint32_t aBase = stage + aOff;
        const uint32_t bBase = stage + A_BY + bOff;
        #pragma unroll
        for (int kk = 0; kk < 2; kk++) {           // two k16 halves of the 32-k tile
            unsigned af[2][4], bf[8][2];
            #pragma unroll
            for (int mi = 0; mi < 2; mi++)
                ldsm_x4(af[mi][0], af[mi][1], af[mi][2], af[mi][3],
                        aBase + mi * (16 * PITCH) + kk * 32);
            #pragma unroll
            for (int p = 0; p < 4; p++)
                ldsm_x4(bf[2 * p][0], bf[2 * p][1], bf[2 * p + 1][0], bf[2 * p + 1][1],
                        bBase + p * (16 * PITCH) + kk * 32);
            #pragma unroll
            for (int mi = 0; mi < 2; mi++)
                #pragma unroll
                for (int ni = 0; ni < 8; ni++)
                    mma16(c[mi][ni][0], c[mi][ni][1], c[mi][ni][2], c[mi][ni][3],
                          af[mi][0], af[mi][1], af[mi][2], af[mi][3],
                          bf[ni][0], bf[ni][1]);
        }
        __syncthreads();
    }

    // epilogue: tanh + w_g dot, reduce over this block's 256 d columns
    float rs[2][2];
    rs[0][0] = rs[0][1] = rs[1][0] = rs[1][1] = 0.f;
    #pragma unroll
    for (int mi = 0; mi < 2; mi++)
        #pragma unroll
        for (int ni = 0; ni < 8; ni++)
            #pragma unroll
            for (int e = 0; e < 4; e++) {
                int dl  = wn * 64 + ni * 8 + q * 2 + (e & 1);
                float x = c[mi][ni][e] + biasS[dl];
                rs[mi][e >> 1] += wgS[dl] * tanhf(x);
            }
    #pragma unroll
    for (int mi = 0; mi < 2; mi++)
        #pragma unroll
        for (int h = 0; h < 2; h++) {
            float v = rs[mi][h];
            v += __shfl_xor_sync(0xffffffffu, v, 1);
            v += __shfl_xor_sync(0xffffffffu, v, 2);
            if (q == 0) redS[wm * 32 + mi * 16 + h * 8 + g][wn] = v;
        }
    __syncthreads();
    if (tid < 128) {
        float ev = redS[tid][0] + redS[tid][1] + redS[tid][2] + redS[tid][3];
        g_epart[(tok0 + tid) * 2 + blockIdx.y] = ev;
    }
}

// ---------------- kernel 4: masked, sharpened softmax over T ----------------
__global__ __launch_bounds__(1024)
void softmax_kernel(const int* __restrict__ lens, float* __restrict__ out) {
    const int b   = blockIdx.x;
    const int len = lens[b];
    const int tid = threadIdx.x;
    __shared__ float sm[32];
    __shared__ float bc;

    float ev[4];
    float m = -1e30f;
    #pragma unroll
    for (int i = 0; i < 4; i++) {
        int t = tid + i * 1024;
        const float* p = &g_epart[((size_t)b * T_ + t) * 2];
        float e = p[0] + p[1];
        ev[i] = e;
        if (t < len) m = fmaxf(m, e);
    }
    #pragma unroll
    for (int o = 16; o > 0; o >>= 1) m = fmaxf(m, __shfl_xor_sync(0xffffffffu, m, o));
    if ((tid & 31) == 0) sm[tid >> 5] = m;
    __syncthreads();
    if (tid < 32) {
        float v = sm[tid];
        #pragma unroll
        for (int o = 16; o > 0; o >>= 1) v = fmaxf(v, __shfl_xor_sync(0xffffffffu, v, o));
        if (tid == 0) bc = v;
    }
    __syncthreads();
    const float M = bc;

    float s = 0.f;
    #pragma unroll
    for (int i = 0; i < 4; i++) {
        int t = tid + i * 1024;
        float w = (t < len) ? expf(2.0f * (ev[i] - M)) : 0.f;
        ev[i] = w;
        s += w;
    }
    #pragma unroll
    for (int o = 16; o > 0; o >>= 1) s += __shfl_xor_sync(0xffffffffu, s, o);
    __syncthreads();
    if ((tid & 31) == 0) sm[tid >> 5] = s;
    __syncthreads();
    if (tid < 32) {
        float v = sm[tid];
        #pragma unroll
        for (int o = 16; o > 0; o >>= 1) v += __shfl_xor_sync(0xffffffffu, v, o);
        if (tid == 0) bc = v;
    }
    __syncthreads();
    const float inv = 1.f / bc;
    #pragma unroll
    for (int i = 0; i < 4; i++) {
        int t = tid + i * 1024;
        out[B_ * D_ + (size_t)b * T_ + t] = ev[i] * inv;
    }
}

// ---------------- kernel 5: context partials (fp16 value) -------------------
__global__ __launch_bounds__(256)
void ctx_part_kernel(const float* __restrict__ wts) {
    const int seg = blockIdx.x, b = blockIdx.y;
    __shared__ float wS[512];
    const int tid = threadIdx.x;
    const int t0  = seg * 512;
    wS[tid]       = wts[(size_t)b * T_ + t0 + tid];
    wS[tid + 256] = wts[(size_t)b * T_ + t0 + tid + 256];
    __syncthreads();
    const __half2* vp =
        reinterpret_cast<const __half2*>(g_val_h + ((size_t)b * T_ + t0) * D_) + tid;
    float ax = 0.f, ay = 0.f;
    #pragma unroll 8
    for (int t = 0; t < 512; t++) {
        float2 f = __half22float2(vp[(size_t)t * 256]);
        float w = wS[t];
        ax += f.x * w;
        ay += f.y * w;
    }
    float* dst = &g_ctxp[((size_t)(b * 8 + seg)) * D_ + 2 * tid];
    dst[0] = ax;
    dst[1] = ay;
}

// ---------------- kernel 6: context reduce ----------------------------------
__global__ __launch_bounds__(512)
void ctx_reduce_kernel(float* __restrict__ out) {
    const int b = blockIdx.x;
    const int d = threadIdx.x;
    float s = 0.f;
    #pragma unroll
    for (int seg = 0; seg < 8; seg++) s += g_ctxp[((size_t)(b * 8 + seg)) * D_ + d];
    out[b * D_ + d] = s;
}

// ---------------- launch -----------------------------------------------------
extern "C" void kernel_launch(void* const* d_in, const int* in_sizes, int n_in,
                              void* d_out, int out_size) {
    const float* value   = (const float*)d_in[0];
    const float* query   = (const float*)d_in[1];
    const int*   lens    = (const int*)  d_in[2];
    const float* attprev = (const float*)d_in[3];
    const float* W_enc   = (const float*)d_in[4];
    const float* b_enc   = (const float*)d_in[5];
    const float* W_dec   = (const float*)d_in[6];
    const float* W_att   = (const float*)d_in[7];
    const float* W_conv  = (const float*)d_in[8];
    const float* w_g     = (const float*)d_in[9];
    // d_in[10] = b_g: constant shift, cancels under softmax -> unused
    float* out = (float*)d_out;   // [0,8192) = context, [8192,73728) = att_weights

    cudaFuncSetAttribute(gemm_e_kernel,
                         cudaFuncAttributeMaxDynamicSharedMemorySize, DYN_SMEM);

    cvt_value_kernel<<<(size_t)B_ * T_ * D_ / 1024, 256>>>(value);
    bias_kernel<<<B_, 256>>>(query, W_dec, b_enc, W_att, W_enc);
    conv_kernel<<<dim3(T_ / 256, B_), 256>>>(attprev, W_conv);
    gemm_e_kernel<<<dim3(T_ / 128, 2, B_), 512, DYN_SMEM>>>(w_g);
    softmax_kernel<<<B_, 1024>>>(lens, out);
    ctx_part_kernel<<<dim3(8, B_), 256>>>(out + B_ * D_);
    ctx_reduce_kernel<<<B_, 512>>>(out);
}

// round 9
// speedup vs baseline: 3.1024x; 1.6572x over previous
#include <cuda_runtime.h>
#include <cuda_fp16.h>
#include <cstdint>

#define B_  16
#define T_  4096
#define D_  512
#define C_  10
#define FW_ 100
#define KW_ 201   // 2*FW+1

// ---------------- scratch (device globals; no allocations allowed) ----------
__device__ float  g_bias[B_ * D_];            // b_enc[d] + (query @ W_dec.T)[b,d]
__device__ __half g_val_h[(size_t)B_ * T_ * D_];   // value in fp16 (64 MB)
__device__ __half g_wenc_h[D_ * D_];          // W_enc fp16 [d][k]
__device__ __half g_conv_h[(size_t)B_ * T_ * 32];  // [b*T+t][32]: 0..9 conv, rest 0
__device__ __half g_watt_h[D_ * 32];          // [d][32]: 0..9 W_att, rest 0
__device__ float  g_epart[B_ * T_ * 2];       // partial e per d-half
__device__ float  g_ctxp[B_ * 16 * D_];       // context partials per t-segment

// ---------------- helpers ---------------------------------------------------
__device__ __forceinline__ uint32_t smem_u32(const void* p) {
    uint32_t a;
    asm("{ .reg .u64 t; cvta.to.shared.u64 t, %1; cvt.u32.u64 %0, t; }" : "=r"(a) : "l"(p));
    return a;
}
__device__ __forceinline__ void cp16(uint32_t dst, const void* src) {
    asm volatile("cp.async.cg.shared.global [%0], [%1], 16;" :: "r"(dst), "l"(src));
}
__device__ __forceinline__ void cp_commit() {
    asm volatile("cp.async.commit_group;" ::: "memory");
}
template <int N>
__device__ __forceinline__ void cp_wait() {
    asm volatile("cp.async.wait_group %0;" :: "n"(N) : "memory");
}
__device__ __forceinline__ void ldsm_x4(unsigned& r0, unsigned& r1, unsigned& r2, unsigned& r3,
                                        uint32_t addr) {
    asm volatile("ldmatrix.sync.aligned.m8n8.x4.shared.b16 {%0,%1,%2,%3}, [%4];"
                 : "=r"(r0), "=r"(r1), "=r"(r2), "=r"(r3) : "r"(addr));
}
__device__ __forceinline__ void mma16(float& c0, float& c1, float& c2, float& c3,
                                      unsigned a0, unsigned a1, unsigned a2, unsigned a3,
                                      unsigned b0, unsigned b1) {
    asm volatile(
        "mma.sync.aligned.m16n8k16.row.col.f32.f16.f16.f32 "
        "{%0,%1,%2,%3}, {%4,%5,%6,%7}, {%8,%9}, {%0,%1,%2,%3};"
        : "+f"(c0), "+f"(c1), "+f"(c2), "+f"(c3)
        : "r"(a0), "r"(a1), "r"(a2), "r"(a3), "r"(b0), "r"(b1));
}

struct alignas(16) Half8 { __half2 h[4]; };
struct alignas(8)  Half4 { __half2 h[2]; };

// ---------------- kernel 0: value -> fp16 (32B per thread) ------------------
__global__ __launch_bounds__(256)
void cvt_value_kernel(const float* __restrict__ v) {
    const size_t i = ((size_t)blockIdx.x * 256 + threadIdx.x) * 8;
    float4 a = *reinterpret_cast<const float4*>(v + i);
    float4 b = *reinterpret_cast<const float4*>(v + i + 4);
    Half8 o;
    o.h[0] = __floats2half2_rn(a.x, a.y);
    o.h[1] = __floats2half2_rn(a.z, a.w);
    o.h[2] = __floats2half2_rn(b.x, b.y);
    o.h[3] = __floats2half2_rn(b.z, b.w);
    *reinterpret_cast<Half8*>(g_val_h + i) = o;
}

// ---------------- kernel 0b: W_enc -> fp16, W_att pad -----------------------
__global__ __launch_bounds__(256)
void wenc_cvt_kernel(const float* __restrict__ W_enc, const float* __restrict__ W_att) {
    const int bid = blockIdx.x;
    const int tid = threadIdx.x;
    if (bid < 256) {
        const int i = (bid * 256 + tid) * 4;
        float4 f = *reinterpret_cast<const float4*>(W_enc + i);
        Half4 o;
        o.h[0] = __floats2half2_rn(f.x, f.y);
        o.h[1] = __floats2half2_rn(f.z, f.w);
        *reinterpret_cast<Half4*>(g_wenc_h + i) = o;
    } else {
        #pragma unroll
        for (int j = 0; j < 64; j++) {
            int idx = tid + j * 256;            // 0..16383
            int r = idx >> 5, cc = idx & 31;
            g_watt_h[idx] = (cc < C_) ? __float2half_rn(W_att[r * C_ + cc])
                                      : __float2half_rn(0.f);
        }
    }
}

// ---------------- kernel 1: bias (128 blocks) -------------------------------
__global__ __launch_bounds__(256)
void bias_kernel(const float* __restrict__ query, const float* __restrict__ W_dec,
                 const float* __restrict__ b_enc) {
    const int b   = blockIdx.y;
    const int grp = blockIdx.x;                // 8 groups of 64 rows
    const int tid = threadIdx.x;
    __shared__ float qS[D_];
    qS[tid]       = query[b * D_ + tid];
    qS[tid + 256] = query[b * D_ + tid + 256];
    __syncthreads();
    const int warp = tid >> 5, lane = tid & 31;
    #pragma unroll
    for (int i = 0; i < 8; i++) {
        int r = grp * 64 + warp * 8 + i;
        float s = 0.f;
        const float* wp = W_dec + (size_t)r * D_;
        #pragma unroll
        for (int k = 0; k < 16; k++) s += wp[lane + k * 32] * qS[lane + k * 32];
        #pragma unroll
        for (int o = 16; o > 0; o >>= 1) s += __shfl_xor_sync(0xffffffffu, s, o);
        if (lane == 0) g_bias[b * D_ + r] = s + b_enc[r];
    }
}

// ---------------- kernel 2: conv -> padded fp16 -----------------------------
__global__ __launch_bounds__(256)
void conv_kernel(const float* __restrict__ att_prev, const float* __restrict__ W_conv) {
    const int b  = blockIdx.y;
    const int t0 = blockIdx.x * 256;
    __shared__ float ap[256 + 2 * FW_];
    __shared__ float wS[C_ * KW_];
    const int tid = threadIdx.x;
    for (int i = tid; i < C_ * KW_; i += 256) wS[i] = W_conv[i];
    for (int i = tid; i < 256 + 2 * FW_; i += 256) {
        int t = t0 + i - FW_;
        ap[i] = (t >= 0 && t < T_) ? att_prev[(size_t)b * T_ + t] : 0.f;
    }
    __syncthreads();
    float acc[C_];
    #pragma unroll
    for (int cc = 0; cc < C_; cc++) acc[cc] = 0.f;
    for (int k = 0; k < KW_; k++) {
        float a = ap[tid + k];
        #pragma unroll
        for (int cc = 0; cc < C_; cc++) acc[cc] += a * wS[cc * KW_ + k];
    }
    __half* dst = &g_conv_h[((size_t)b * T_ + t0 + tid) * 32];
    #pragma unroll
    for (int cc = 0; cc < C_; cc++) dst[cc] = __float2half_rn(acc[cc]);
    #pragma unroll
    for (int cc = C_; cc < 32; cc++) dst[cc] = __float2half_rn(0.f);
}

// ---------------- kernel 3: pipelined FP16 GEMM + e epilogue ----------------
// Tile per CTA: 128 tokens x 256 d, K = 544 (17 k-tiles of 32), 512 threads.
// 4-stage cp.async, ONE barrier per k-tile (stage-after-barrier ordering).
#define PITCH  80
#define A_BY   (128 * PITCH)             // 10240
#define Bb_BY  (256 * PITCH)             // 20480
#define ST_BY  (A_BY + Bb_BY)            // 30720
#define NSTAGE 4
#define DYN_SMEM (NSTAGE * ST_BY)        // 122880

__device__ __forceinline__ void stage_cp(const __half* __restrict__ srcA, int ldA,
                                         const __half* __restrict__ srcB, int ldB,
                                         uint32_t st, int tid) {
    {
        int r = tid >> 2, c4 = tid & 3;
        cp16(st + r * PITCH + c4 * 16, srcA + (size_t)r * ldA + c4 * 8);
    }
    #pragma unroll
    for (int i = 0; i < 2; i++) {
        int slot = tid + i * 512;
        int r = slot >> 2, c4 = slot & 3;
        cp16(st + A_BY + r * PITCH + c4 * 16, srcB + (size_t)r * ldB + c4 * 8);
    }
}

__global__ __launch_bounds__(512, 1)
void gemm_e_kernel(const float* __restrict__ w_g) {
    extern __shared__ char dynsmem[];
    const uint32_t sb = smem_u32(dynsmem);

    __shared__ float biasS[256];
    __shared__ float wgS[256];
    __shared__ float redS[128][4];

    const int tid  = threadIdx.x;
    const int lane = tid & 31;
    const int warp = tid >> 5;
    const int wm = warp & 3;
    const int wn = warp >> 2;
    const int q  = lane & 3;
    const int g  = lane >> 2;

    const int b  = blockIdx.z;
    const int t0 = blockIdx.x * 128;
    const int d0 = blockIdx.y * 256;
    const size_t tok0 = (size_t)b * T_ + t0;

    if (tid < 256) {
        biasS[tid] = g_bias[b * D_ + d0 + tid];
        wgS[tid]   = w_g[d0 + tid];
    }

    float c[2][8][4];
    #pragma unroll
    for (int mi = 0; mi < 2; mi++)
        #pragma unroll
        for (int ni = 0; ni < 8; ni++)
            #pragma unroll
            for (int e = 0; e < 4; e++) c[mi][ni][e] = 0.f;

    const __half* Ag = g_val_h + tok0 * D_;
    const __half* Bg = g_wenc_h + (size_t)d0 * D_;

    // prologue: stage tiles 0..2
    stage_cp(Ag,      D_, Bg,      D_, sb,             tid); cp_commit();
    stage_cp(Ag + 32, D_, Bg + 32, D_, sb + ST_BY,     tid); cp_commit();
    stage_cp(Ag + 64, D_, Bg + 64, D_, sb + 2 * ST_BY, tid); cp_commit();

    const uint32_t aOff = (uint32_t)((wm * 32 + (lane & 15)) * PITCH + ((lane >> 4) << 4));
    const uint32_t bOff = (uint32_t)((wn * 64 + (lane & 7) + (((lane >> 4) & 1) << 3)) * PITCH
                                     + (((lane >> 3) & 1) << 4));

    for (int kt = 0; kt < 17; kt++) {
        cp_wait<2>();
        __syncthreads();

        const uint32_t stage = sb + (kt & 3) * ST_BY;
        const uint32_t aBase = stage + aOff;
        const uint32_t bBase = stage + A_BY + bOff;

        // ---- kk = 0 ----
        {
            unsigned af[2][4], bf[8][2];
            #pragma unroll
            for (int mi = 0; mi < 2; mi++)
                ldsm_x4(af[mi][0], af[mi][1], af[mi][2], af[mi][3],
                        aBase + mi * (16 * PITCH));
            #pragma unroll
            for (int p = 0; p < 4; p++)
                ldsm_x4(bf[2 * p][0], bf[2 * p][1], bf[2 * p + 1][0], bf[2 * p + 1][1],
                        bBase + p * (16 * PITCH));
            #pragma unroll
            for (int mi = 0; mi < 2; mi++)
                #pragma unroll
                for (int ni = 0; ni < 8; ni++)
                    mma16(c[mi][ni][0], c[mi][ni][1], c[mi][ni][2], c[mi][ni][3],
                          af[mi][0], af[mi][1], af[mi][2], af[mi][3],
                          bf[ni][0], bf[ni][1]);
        }

        // ---- stage tile kt+3 into stage (kt+3)&3 == (kt-1)&3 (drained) ----
        {
            const int j = kt + 3;
            if (j <= 16) {
                const uint32_t st = sb + (j & 3) * ST_BY;
                if (j < 16)
                    stage_cp(Ag + j * 32, D_, Bg + j * 32, D_, st, tid);
                else
                    stage_cp(g_conv_h + tok0 * 32, 32,
                             g_watt_h + (size_t)d0 * 32, 32, st, tid);
            }
            cp_commit();
        }

        // ---- kk = 1 ----
        {
            unsigned af[2][4], bf[8][2];
            #pragma unroll
            for (int mi = 0; mi < 2; mi++)
                ldsm_x4(af[mi][0], af[mi][1], af[mi][2], af[mi][3],
                        aBase + mi * (16 * PITCH) + 32);
            #pragma unroll
            for (int p = 0; p < 4; p++)
                ldsm_x4(bf[2 * p][0], bf[2 * p][1], bf[2 * p + 1][0], bf[2 * p + 1][1],
                        bBase + p * (16 * PITCH) + 32);
            #pragma unroll
            for (int mi = 0; mi < 2; mi++)
                #pragma unroll
                for (int ni = 0; ni < 8; ni++)
                    mma16(c[mi][ni][0], c[mi][ni][1], c[mi][ni][2], c[mi][ni][3],
                          af[mi][0], af[mi][1], af[mi][2], af[mi][3],
                          bf[ni][0], bf[ni][1]);
        }
    }

    // epilogue: tanh + w_g dot, reduce over this block's 256 d columns
    float rs[2][2];
    rs[0][0] = rs[0][1] = rs[1][0] = rs[1][1] = 0.f;
    #pragma unroll
    for (int mi = 0; mi < 2; mi++)
        #pragma unroll
        for (int ni = 0; ni < 8; ni++)
            #pragma unroll
            for (int e = 0; e < 4; e++) {
                int dl  = wn * 64 + ni * 8 + q * 2 + (e & 1);
                float x = c[mi][ni][e] + biasS[dl];
                rs[mi][e >> 1] += wgS[dl] * tanhf(x);
            }
    #pragma unroll
    for (int mi = 0; mi < 2; mi++)
        #pragma unroll
        for (int h = 0; h < 2; h++) {
            float v = rs[mi][h];
            v += __shfl_xor_sync(0xffffffffu, v, 1);
            v += __shfl_xor_sync(0xffffffffu, v, 2);
            if (q == 0) redS[wm * 32 + mi * 16 + h * 8 + g][wn] = v;
        }
    __syncthreads();
    if (tid < 128) {
        float ev = redS[tid][0] + redS[tid][1] + redS[tid][2] + redS[tid][3];
        g_epart[(tok0 + tid) * 2 + blockIdx.y] = ev;
    }
}

// ---------------- kernel 4: masked, sharpened softmax over T ----------------
__global__ __launch_bounds__(1024)
void softmax_kernel(const int* __restrict__ lens, float* __restrict__ out) {
    const int b   = blockIdx.x;
    const int len = lens[b];
    const int tid = threadIdx.x;
    __shared__ float sm[32];
    __shared__ float bc;

    float ev[4];
    float m = -1e30f;
    #pragma unroll
    for (int i = 0; i < 4; i++) {
        int t = tid + i * 1024;
        const float* p = &g_epart[((size_t)b * T_ + t) * 2];
        float e = p[0] + p[1];
        ev[i] = e;
        if (t < len) m = fmaxf(m, e);
    }
    #pragma unroll
    for (int o = 16; o > 0; o >>= 1) m = fmaxf(m, __shfl_xor_sync(0xffffffffu, m, o));
    if ((tid & 31) == 0) sm[tid >> 5] = m;
    __syncthreads();
    if (tid < 32) {
        float v = sm[tid];
        #pragma unroll
        for (int o = 16; o > 0; o >>= 1) v = fmaxf(v, __shfl_xor_sync(0xffffffffu, v, o));
        if (tid == 0) bc = v;
    }
    __syncthreads();
    const float M = bc;

    float s = 0.f;
    #pragma unroll
    for (int i = 0; i < 4; i++) {
        int t = tid + i * 1024;
        float w = (t < len) ? expf(2.0f * (ev[i] - M)) : 0.f;
        ev[i] = w;
        s += w;
    }
    #pragma unroll
    for (int o = 16; o > 0; o >>= 1) s += __shfl_xor_sync(0xffffffffu, s, o);
    __syncthreads();
    if ((tid & 31) == 0) sm[tid >> 5] = s;
    __syncthreads();
    if (tid < 32) {
        float v = sm[tid];
        #pragma unroll
        for (int o = 16; o > 0; o >>= 1) v += __shfl_xor_sync(0xffffffffu, v, o);
        if (tid == 0) bc = v;
    }
    __syncthreads();
    const float inv = 1.f / bc;
    #pragma unroll
    for (int i = 0; i < 4; i++) {
        int t = tid + i * 1024;
        out[B_ * D_ + (size_t)b * T_ + t] = ev[i] * inv;
    }
}

// ---------------- kernel 5: context partials (fp16 value, 16 segs) ----------
__global__ __launch_bounds__(256)
void ctx_part_kernel(const float* __restrict__ wts) {
    const int seg = blockIdx.x, b = blockIdx.y;
    __shared__ float wS[256];
    const int tid = threadIdx.x;
    const int t0  = seg * 256;
    wS[tid] = wts[(size_t)b * T_ + t0 + tid];
    __syncthreads();
    const __half2* vp =
        reinterpret_cast<const __half2*>(g_val_h + ((size_t)b * T_ + t0) * D_) + tid;
    float ax = 0.f, ay = 0.f;
    #pragma unroll 8
    for (int t = 0; t < 256; t++) {
        float2 f = __half22float2(vp[(size_t)t * 256]);
        float w = wS[t];
        ax += f.x * w;
        ay += f.y * w;
    }
    float* dst = &g_ctxp[((size_t)(b * 16 + seg)) * D_ + 2 * tid];
    dst[0] = ax;
    dst[1] = ay;
}

// ---------------- kernel 6: context reduce ----------------------------------
__global__ __launch_bounds__(512)
void ctx_reduce_kernel(float* __restrict__ out) {
    const int b = blockIdx.x;
    const int d = threadIdx.x;
    float s = 0.f;
    #pragma unroll
    for (int seg = 0; seg < 16; seg++) s += g_ctxp[((size_t)(b * 16 + seg)) * D_ + d];
    out[b * D_ + d] = s;
}

// ---------------- launch -----------------------------------------------------
extern "C" void kernel_launch(void* const* d_in, const int* in_sizes, int n_in,
                              void* d_out, int out_size) {
    const float* value   = (const float*)d_in[0];
    const float* query   = (const float*)d_in[1];
    const int*   lens    = (const int*)  d_in[2];
    const float* attprev = (const float*)d_in[3];
    const float* W_enc   = (const float*)d_in[4];
    const float* b_enc   = (const float*)d_in[5];
    const float* W_dec   = (const float*)d_in[6];
    const float* W_att   = (const float*)d_in[7];
    const float* W_conv  = (const float*)d_in[8];
    const float* w_g     = (const float*)d_in[9];
    // d_in[10] = b_g: constant shift, cancels under softmax -> unused
    float* out = (float*)d_out;   // [0,8192) = context, [8192,73728) = att_weights

    cudaFuncSetAttribute(gemm_e_kernel,
                         cudaFuncAttributeMaxDynamicSharedMemorySize, DYN_SMEM);

    cvt_value_kernel<<<(size_t)B_ * T_ * D_ / 2048, 256>>>(value);
    wenc_cvt_kernel<<<257, 256>>>(W_enc, W_att);
    bias_kernel<<<dim3(8, B_), 256>>>(query, W_dec, b_enc);
    conv_kernel<<<dim3(T_ / 256, B_), 256>>>(attprev, W_conv);
    gemm_e_kernel<<<dim3(T_ / 128, 2, B_), 512, DYN_SMEM>>>(w_g);
    softmax_kernel<<<B_, 1024>>>(lens, out);
    ctx_part_kernel<<<dim3(16, B_), 256>>>(out + B_ * D_);
    ctx_reduce_kernel<<<B_, 512>>>(out);
}

// round 10
// speedup vs baseline: 3.4110x; 1.0995x over previous
#include <cuda_runtime.h>
#include <cuda_fp16.h>
#include <cstdint>

#define B_  16
#define T_  4096
#define D_  512
#define C_  10
#define FW_ 100
#define KW_ 201   // 2*FW+1

// ---------------- scratch (device globals; no allocations allowed) ----------
__device__ float  g_bias[B_ * D_];            // b_enc[d] + (query @ W_dec.T)[b,d]
__device__ __half g_val_h[(size_t)B_ * T_ * D_];   // value in fp16 (64 MB)
__device__ __half g_wenc_h[D_ * D_];          // W_enc fp16 [d][k]
__device__ __half g_conv_h[(size_t)B_ * T_ * 32];  // [b*T+t][32]: 0..9 conv, rest 0
__device__ __half g_watt_h[D_ * 32];          // [d][32]: 0..9 W_att, rest 0
__device__ float  g_epart[B_ * T_ * 2];       // partial e per d-half
__device__ float  g_ctxp[B_ * 16 * D_];       // context partials per t-segment

// ---------------- helpers ---------------------------------------------------
__device__ __forceinline__ uint32_t smem_u32(const void* p) {
    uint32_t a;
    asm("{ .reg .u64 t; cvta.to.shared.u64 t, %1; cvt.u32.u64 %0, t; }" : "=r"(a) : "l"(p));
    return a;
}
__device__ __forceinline__ void cp16(uint32_t dst, const void* src) {
    asm volatile("cp.async.cg.shared.global [%0], [%1], 16;" :: "r"(dst), "l"(src));
}
__device__ __forceinline__ void cp_commit() {
    asm volatile("cp.async.commit_group;" ::: "memory");
}
template <int N>
__device__ __forceinline__ void cp_wait() {
    asm volatile("cp.async.wait_group %0;" :: "n"(N) : "memory");
}
__device__ __forceinline__ void ldsm_x4(unsigned& r0, unsigned& r1, unsigned& r2, unsigned& r3,
                                        uint32_t addr) {
    asm volatile("ldmatrix.sync.aligned.m8n8.x4.shared.b16 {%0,%1,%2,%3}, [%4];"
                 : "=r"(r0), "=r"(r1), "=r"(r2), "=r"(r3) : "r"(addr));
}
__device__ __forceinline__ void mma16(float& c0, float& c1, float& c2, float& c3,
                                      unsigned a0, unsigned a1, unsigned a2, unsigned a3,
                                      unsigned b0, unsigned b1) {
    asm volatile(
        "mma.sync.aligned.m16n8k16.row.col.f32.f16.f16.f32 "
        "{%0,%1,%2,%3}, {%4,%5,%6,%7}, {%8,%9}, {%0,%1,%2,%3};"
        : "+f"(c0), "+f"(c1), "+f"(c2), "+f"(c3)
        : "r"(a0), "r"(a1), "r"(a2), "r"(a3), "r"(b0), "r"(b1));
}

struct alignas(16) Half8 { __half2 h[4]; };
struct alignas(8)  Half4 { __half2 h[2]; };

// ---------------- merged prep kernel ----------------------------------------
// grid layout (blocks of 256 threads):
//   [0, 512)            conv:  b = i>>5, tblk = i&31 (128 tokens each)
//   [512, 640)          bias:  b = (i-512)>>3, grp = (i-512)&7 (64 rows each)
//   [640, 896)          wenc cvt (256 blocks)
//   [896]               watt pad
//   [897, 897+16384)    cvt_value
#define PREP_CONV   0
#define PREP_BIAS   512
#define PREP_WENC   640
#define PREP_WATT   896
#define PREP_CVT    897
#define PREP_GRID   (PREP_CVT + 16384)

__global__ __launch_bounds__(256)
void prep_kernel(const float* __restrict__ value, const float* __restrict__ W_enc,
                 const float* __restrict__ W_att, const float* __restrict__ query,
                 const float* __restrict__ W_dec, const float* __restrict__ b_enc,
                 const float* __restrict__ att_prev, const float* __restrict__ W_conv) {
    __shared__ float smem[3664];    // conv: ap[328] + wS[2010] + red[1280]
    const int bid = blockIdx.x;
    const int tid = threadIdx.x;

    if (bid < PREP_BIAS) {
        // ---- conv: 128 tokens per block, 2-way tap split ----
        const int b  = bid >> 5;
        const int t0 = (bid & 31) * 128;
        float* ap  = smem;               // 328
        float* wS  = smem + 328;         // 2010
        float* red = smem + 2338;        // 128 x 10
        for (int i = tid; i < C_ * KW_; i += 256) wS[i] = W_conv[i];
        for (int i = tid; i < 128 + 2 * FW_; i += 256) {
            int t = t0 + i - FW_;
            ap[i] = (t >= 0 && t < T_) ? att_prev[(size_t)b * T_ + t] : 0.f;
        }
        __syncthreads();
        const int tl   = tid & 127;
        const int part = tid >> 7;       // 0: taps [0,101), 1: taps [101,201)
        const int k0 = part * 101;
        const int k1 = part ? KW_ : 101;
        float acc[C_];
        #pragma unroll
        for (int cc = 0; cc < C_; cc++) acc[cc] = 0.f;
        for (int k = k0; k < k1; k++) {
            float a = ap[tl + k];
            #pragma unroll
            for (int cc = 0; cc < C_; cc++) acc[cc] += a * wS[cc * KW_ + k];
        }
        if (part == 1) {
            #pragma unroll
            for (int cc = 0; cc < C_; cc++) red[tl * C_ + cc] = acc[cc];
        }
        __syncthreads();
        if (part == 0) {
            __half* dst = &g_conv_h[((size_t)b * T_ + t0 + tl) * 32];
            #pragma unroll
            for (int cc = 0; cc < C_; cc++)
                dst[cc] = __float2half_rn(acc[cc] + red[tl * C_ + cc]);
            #pragma unroll
            for (int cc = C_; cc < 32; cc++) dst[cc] = __float2half_rn(0.f);
        }
    } else if (bid < PREP_WENC) {
        // ---- bias: 64 rows per block ----
        const int li  = bid - PREP_BIAS;
        const int b   = li >> 3;
        const int grp = li & 7;
        float* qS = smem;
        qS[tid]       = query[b * D_ + tid];
        qS[tid + 256] = query[b * D_ + tid + 256];
        __syncthreads();
        const int warp = tid >> 5, lane = tid & 31;
        #pragma unroll
        for (int i = 0; i < 8; i++) {
            int r = grp * 64 + warp * 8 + i;
            float s = 0.f;
            const float* wp = W_dec + (size_t)r * D_;
            #pragma unroll
            for (int k = 0; k < 16; k++) s += wp[lane + k * 32] * qS[lane + k * 32];
            #pragma unroll
            for (int o = 16; o > 0; o >>= 1) s += __shfl_xor_sync(0xffffffffu, s, o);
            if (lane == 0) g_bias[b * D_ + r] = s + b_enc[r];
        }
    } else if (bid < PREP_WATT) {
        // ---- W_enc -> fp16 ----
        const int i = ((bid - PREP_WENC) * 256 + tid) * 4;
        float4 f = *reinterpret_cast<const float4*>(W_enc + i);
        Half4 o;
        o.h[0] = __floats2half2_rn(f.x, f.y);
        o.h[1] = __floats2half2_rn(f.z, f.w);
        *reinterpret_cast<Half4*>(g_wenc_h + i) = o;
    } else if (bid == PREP_WATT) {
        // ---- W_att pad ----
        #pragma unroll
        for (int j = 0; j < 64; j++) {
            int idx = tid + j * 256;
            int r = idx >> 5, cc = idx & 31;
            g_watt_h[idx] = (cc < C_) ? __float2half_rn(W_att[r * C_ + cc])
                                      : __float2half_rn(0.f);
        }
    } else {
        // ---- value -> fp16, 32B per thread ----
        const size_t i = ((size_t)(bid - PREP_CVT) * 256 + tid) * 8;
        float4 a = *reinterpret_cast<const float4*>(value + i);
        float4 b4 = *reinterpret_cast<const float4*>(value + i + 4);
        Half8 o;
        o.h[0] = __floats2half2_rn(a.x, a.y);
        o.h[1] = __floats2half2_rn(a.z, a.w);
        o.h[2] = __floats2half2_rn(b4.x, b4.y);
        o.h[3] = __floats2half2_rn(b4.z, b4.w);
        *reinterpret_cast<Half8*>(g_val_h + i) = o;
    }
}

// ---------------- kernel 3: pipelined FP16 GEMM + e epilogue ----------------
#define PITCH  80
#define A_BY   (128 * PITCH)             // 10240
#define Bb_BY  (256 * PITCH)             // 20480
#define ST_BY  (A_BY + Bb_BY)            // 30720
#define NSTAGE 4
#define DYN_SMEM (NSTAGE * ST_BY)        // 122880

__device__ __forceinline__ void stage_cp(const __half* __restrict__ srcA, int ldA,
                                         const __half* __restrict__ srcB, int ldB,
                                         uint32_t st, int tid) {
    {
        int r = tid >> 2, c4 = tid & 3;
        cp16(st + r * PITCH + c4 * 16, srcA + (size_t)r * ldA + c4 * 8);
    }
    #pragma unroll
    for (int i = 0; i < 2; i++) {
        int slot = tid + i * 512;
        int r = slot >> 2, c4 = slot & 3;
        cp16(st + A_BY + r * PITCH + c4 * 16, srcB + (size_t)r * ldB + c4 * 8);
    }
}

__global__ __launch_bounds__(512, 1)
void gemm_e_kernel(const float* __restrict__ w_g) {
    extern __shared__ char dynsmem[];
    const uint32_t sb = smem_u32(dynsmem);

    __shared__ float biasS[256];
    __shared__ float wgS[256];
    __shared__ float redS[128][4];

    const int tid  = threadIdx.x;
    const int lane = tid & 31;
    const int warp = tid >> 5;
    const int wm = warp & 3;
    const int wn = warp >> 2;
    const int q  = lane & 3;
    const int g  = lane >> 2;

    const int b  = blockIdx.z;
    const int t0 = blockIdx.x * 128;
    const int d0 = blockIdx.y * 256;
    const size_t tok0 = (size_t)b * T_ + t0;

    if (tid < 256) {
        biasS[tid] = g_bias[b * D_ + d0 + tid];
        wgS[tid]   = w_g[d0 + tid];
    }

    float c[2][8][4];
    #pragma unroll
    for (int mi = 0; mi < 2; mi++)
        #pragma unroll
        for (int ni = 0; ni < 8; ni++)
            #pragma unroll
            for (int e = 0; e < 4; e++) c[mi][ni][e] = 0.f;

    const __half* Ag = g_val_h + tok0 * D_;
    const __half* Bg = g_wenc_h + (size_t)d0 * D_;

    stage_cp(Ag,      D_, Bg,      D_, sb,             tid); cp_commit();
    stage_cp(Ag + 32, D_, Bg + 32, D_, sb + ST_BY,     tid); cp_commit();
    stage_cp(Ag + 64, D_, Bg + 64, D_, sb + 2 * ST_BY, tid); cp_commit();

    const uint32_t aOff = (uint32_t)((wm * 32 + (lane & 15)) * PITCH + ((lane >> 4) << 4));
    const uint32_t bOff = (uint32_t)((wn * 64 + (lane & 7) + (((lane >> 4) & 1) << 3)) * PITCH
                                     + (((lane >> 3) & 1) << 4));

    for (int kt = 0; kt < 17; kt++) {
        cp_wait<2>();
        __syncthreads();

        const uint32_t stage = sb + (kt & 3) * ST_BY;
        const uint32_t aBase = stage + aOff;
        const uint32_t bBase = stage + A_BY + bOff;

        // ---- kk = 0 ----
        {
            unsigned af[2][4], bf[8][2];
            #pragma unroll
            for (int mi = 0; mi < 2; mi++)
                ldsm_x4(af[mi][0], af[mi][1], af[mi][2], af[mi][3],
                        aBase + mi * (16 * PITCH));
            #pragma unroll
            for (int p = 0; p < 4; p++)
                ldsm_x4(bf[2 * p][0], bf[2 * p][1], bf[2 * p + 1][0], bf[2 * p + 1][1],
                        bBase + p * (16 * PITCH));
            #pragma unroll
            for (int mi = 0; mi < 2; mi++)
                #pragma unroll
                for (int ni = 0; ni < 8; ni++)
                    mma16(c[mi][ni][0], c[mi][ni][1], c[mi][ni][2], c[mi][ni][3],
                          af[mi][0], af[mi][1], af[mi][2], af[mi][3],
                          bf[ni][0], bf[ni][1]);
        }

        // ---- stage tile kt+3 into drained stage ----
        {
            const int j = kt + 3;
            if (j <= 16) {
                const uint32_t st = sb + (j & 3) * ST_BY;
                if (j < 16)
                    stage_cp(Ag + j * 32, D_, Bg + j * 32, D_, st, tid);
                else
                    stage_cp(g_conv_h + tok0 * 32, 32,
                             g_watt_h + (size_t)d0 * 32, 32, st, tid);
            }
            cp_commit();
        }

        // ---- kk = 1 ----
        {
            unsigned af[2][4], bf[8][2];
            #pragma unroll
            for (int mi = 0; mi < 2; mi++)
                ldsm_x4(af[mi][0], af[mi][1], af[mi][2], af[mi][3],
                        aBase + mi * (16 * PITCH) + 32);
            #pragma unroll
            for (int p = 0; p < 4; p++)
                ldsm_x4(bf[2 * p][0], bf[2 * p][1], bf[2 * p + 1][0], bf[2 * p + 1][1],
                        bBase + p * (16 * PITCH) + 32);
            #pragma unroll
            for (int mi = 0; mi < 2; mi++)
                #pragma unroll
                for (int ni = 0; ni < 8; ni++)
                    mma16(c[mi][ni][0], c[mi][ni][1], c[mi][ni][2], c[mi][ni][3],
                          af[mi][0], af[mi][1], af[mi][2], af[mi][3],
                          bf[ni][0], bf[ni][1]);
        }
    }

    // epilogue
    float rs[2][2];
    rs[0][0] = rs[0][1] = rs[1][0] = rs[1][1] = 0.f;
    #pragma unroll
    for (int mi = 0; mi < 2; mi++)
        #pragma unroll
        for (int ni = 0; ni < 8; ni++)
            #pragma unroll
            for (int e = 0; e < 4; e++) {
                int dl  = wn * 64 + ni * 8 + q * 2 + (e & 1);
                float x = c[mi][ni][e] + biasS[dl];
                rs[mi][e >> 1] += wgS[dl] * tanhf(x);
            }
    #pragma unroll
    for (int mi = 0; mi < 2; mi++)
        #pragma unroll
        for (int h = 0; h < 2; h++) {
            float v = rs[mi][h];
            v += __shfl_xor_sync(0xffffffffu, v, 1);
            v += __shfl_xor_sync(0xffffffffu, v, 2);
            if (q == 0) redS[wm * 32 + mi * 16 + h * 8 + g][wn] = v;
        }
    __syncthreads();
    if (tid < 128) {
        float ev = redS[tid][0] + redS[tid][1] + redS[tid][2] + redS[tid][3];
        g_epart[(tok0 + tid) * 2 + blockIdx.y] = ev;
    }
}

// ---------------- kernel 4: masked, sharpened softmax over T ----------------
__global__ __launch_bounds__(1024)
void softmax_kernel(const int* __restrict__ lens, float* __restrict__ out) {
    const int b   = blockIdx.x;
    const int len = lens[b];
    const int tid = threadIdx.x;
    __shared__ float sm[32];
    __shared__ float bc;

    float ev[4];
    float m = -1e30f;
    #pragma unroll
    for (int i = 0; i < 4; i++) {
        int t = tid + i * 1024;
        const float* p = &g_epart[((size_t)b * T_ + t) * 2];
        float e = p[0] + p[1];
        ev[i] = e;
        if (t < len) m = fmaxf(m, e);
    }
    #pragma unroll
    for (int o = 16; o > 0; o >>= 1) m = fmaxf(m, __shfl_xor_sync(0xffffffffu, m, o));
    if ((tid & 31) == 0) sm[tid >> 5] = m;
    __syncthreads();
    if (tid < 32) {
        float v = sm[tid];
        #pragma unroll
        for (int o = 16; o > 0; o >>= 1) v = fmaxf(v, __shfl_xor_sync(0xffffffffu, v, o));
        if (tid == 0) bc = v;
    }
    __syncthreads();
    const float M = bc;

    float s = 0.f;
    #pragma unroll
    for (int i = 0; i < 4; i++) {
        int t = tid + i * 1024;
        float w = (t < len) ? expf(2.0f * (ev[i] - M)) : 0.f;
        ev[i] = w;
        s += w;
    }
    #pragma unroll
    for (int o = 16; o > 0; o >>= 1) s += __shfl_xor_sync(0xffffffffu, s, o);
    __syncthreads();
    if ((tid & 31) == 0) sm[tid >> 5] = s;
    __syncthreads();
    if (tid < 32) {
        float v = sm[tid];
        #pragma unroll
        for (int o = 16; o > 0; o >>= 1) v += __shfl_xor_sync(0xffffffffu, v, o);
        if (tid == 0) bc = v;
    }
    __syncthreads();
    const float inv = 1.f / bc;
    #pragma unroll
    for (int i = 0; i < 4; i++) {
        int t = tid + i * 1024;
        out[B_ * D_ + (size_t)b * T_ + t] = ev[i] * inv;
    }
}

// ---------------- kernel 5: context partials (fp16 value, 16 segs) ----------
__global__ __launch_bounds__(256)
void ctx_part_kernel(const float* __restrict__ wts) {
    const int seg = blockIdx.x, b = blockIdx.y;
    __shared__ float wS[256];
    const int tid = threadIdx.x;
    const int t0  = seg * 256;
    wS[tid] = wts[(size_t)b * T_ + t0 + tid];
    __syncthreads();
    const __half2* vp =
        reinterpret_cast<const __half2*>(g_val_h + ((size_t)b * T_ + t0) * D_) + tid;
    float ax = 0.f, ay = 0.f;
    #pragma unroll 8
    for (int t = 0; t < 256; t++) {
        float2 f = __half22float2(vp[(size_t)t * 256]);
        float w = wS[t];
        ax += f.x * w;
        ay += f.y * w;
    }
    float* dst = &g_ctxp[((size_t)(b * 16 + seg)) * D_ + 2 * tid];
    dst[0] = ax;
    dst[1] = ay;
}

// ---------------- kernel 6: context reduce ----------------------------------
__global__ __launch_bounds__(512)
void ctx_reduce_kernel(float* __restrict__ out) {
    const int b = blockIdx.x;
    const int d = threadIdx.x;
    float s = 0.f;
    #pragma unroll
    for (int seg = 0; seg < 16; seg++) s += g_ctxp[((size_t)(b * 16 + seg)) * D_ + d];
    out[b * D_ + d] = s;
}

// ---------------- launch -----------------------------------------------------
extern "C" void kernel_launch(void* const* d_in, const int* in_sizes, int n_in,
                              void* d_out, int out_size) {
    const float* value   = (const float*)d_in[0];
    const float* query   = (const float*)d_in[1];
    const int*   lens    = (const int*)  d_in[2];
    const float* attprev = (const float*)d_in[3];
    const float* W_enc   = (const float*)d_in[4];
    const float* b_enc   = (const float*)d_in[5];
    const float* W_dec   = (const float*)d_in[6];
    const float* W_att   = (const float*)d_in[7];
    const float* W_conv  = (const float*)d_in[8];
    const float* w_g     = (const float*)d_in[9];
    // d_in[10] = b_g: constant shift, cancels under softmax -> unused
    float* out = (float*)d_out;   // [0,8192) = context, [8192,73728) = att_weights

    cudaFuncSetAttribute(gemm_e_kernel,
                         cudaFuncAttributeMaxDynamicSharedMemorySize, DYN_SMEM);

    prep_kernel<<<PREP_GRID, 256>>>(value, W_enc, W_att, query, W_dec, b_enc,
                                    attprev, W_conv);
    gemm_e_kernel<<<dim3(T_ / 128, 2, B_), 512, DYN_SMEM>>>(w_g);
    softmax_kernel<<<B_, 1024>>>(lens, out);
    ctx_part_kernel<<<dim3(16, B_), 256>>>(out + B_ * D_);
    ctx_reduce_kernel<<<B_, 512>>>(out);
}

// round 12
// speedup vs baseline: 3.4479x; 1.0108x over previous
#include <cuda_runtime.h>
#include <cuda_fp16.h>
#include <cstdint>

#define B_  16
#define T_  4096
#define D_  512
#define C_  10
#define FW_ 100
#define KW_ 201   // 2*FW+1

// ---------------- scratch (device globals; no allocations allowed) ----------
__device__ float  g_bias[B_ * D_];            // b_enc[d] + (query @ W_dec.T)[b,d]
__device__ __half g_val_h[(size_t)B_ * T_ * D_];   // value in fp16 (64 MB)
__device__ __half g_wenc_h[D_ * D_];          // W_enc fp16 [d][k]
__device__ __half g_conv_h[(size_t)B_ * T_ * 32];  // [b*T+t][32]: 0..9 conv, rest 0
__device__ __half g_watt_h[D_ * 32];          // [d][32]: 0..9 W_att, rest 0
__device__ float  g_epart[B_ * T_ * 2];       // partial e per d-half
__device__ float  g_ctxp[B_ * 32 * D_];       // context partials per t-segment

// ---------------- helpers ---------------------------------------------------
__device__ __forceinline__ uint32_t smem_u32(const void* p) {
    uint32_t a;
    asm("{ .reg .u64 t; cvta.to.shared.u64 t, %1; cvt.u32.u64 %0, t; }" : "=r"(a) : "l"(p));
    return a;
}
__device__ __forceinline__ void cp16(uint32_t dst, const void* src) {
    asm volatile("cp.async.cg.shared.global [%0], [%1], 16;" :: "r"(dst), "l"(src));
}
__device__ __forceinline__ void cp_commit() {
    asm volatile("cp.async.commit_group;" ::: "memory");
}
template <int N>
__device__ __forceinline__ void cp_wait() {
    asm volatile("cp.async.wait_group %0;" :: "n"(N) : "memory");
}
__device__ __forceinline__ void ldsm_x4(unsigned& r0, unsigned& r1, unsigned& r2, unsigned& r3,
                                        uint32_t addr) {
    asm volatile("ldmatrix.sync.aligned.m8n8.x4.shared.b16 {%0,%1,%2,%3}, [%4];"
                 : "=r"(r0), "=r"(r1), "=r"(r2), "=r"(r3) : "r"(addr));
}
__device__ __forceinline__ void mma16(float& c0, float& c1, float& c2, float& c3,
                                      unsigned a0, unsigned a1, unsigned a2, unsigned a3,
                                      unsigned b0, unsigned b1) {
    asm volatile(
        "mma.sync.aligned.m16n8k16.row.col.f32.f16.f16.f32 "
        "{%0,%1,%2,%3}, {%4,%5,%6,%7}, {%8,%9}, {%0,%1,%2,%3};"
        : "+f"(c0), "+f"(c1), "+f"(c2), "+f"(c3)
        : "r"(a0), "r"(a1), "r"(a2), "r"(a3), "r"(b0), "r"(b1));
}

struct alignas(16) Half8 { __half2 h[4]; };
struct alignas(8)  Half4 { __half2 h[2]; };

// ---------------- merged prep kernel ----------------------------------------
#define PREP_CONV   0
#define PREP_BIAS   512
#define PREP_WENC   640
#define PREP_WATT   896
#define PREP_CVT    897
#define PREP_GRID   (PREP_CVT + 16384)

__global__ __launch_bounds__(256)
void prep_kernel(const float* __restrict__ value, const float* __restrict__ W_enc,
                 const float* __restrict__ W_att, const float* __restrict__ query,
                 const float* __restrict__ W_dec, const float* __restrict__ b_enc,
                 const float* __restrict__ att_prev, const float* __restrict__ W_conv) {
    __shared__ float smem[3664];    // conv: ap[328] + wS[2010] + red[1280]
    const int bid = blockIdx.x;
    const int tid = threadIdx.x;

    if (bid < PREP_BIAS) {
        // ---- conv: 128 tokens per block, 2-way tap split ----
        const int b  = bid >> 5;
        const int t0 = (bid & 31) * 128;
        float* ap  = smem;               // 328
        float* wS  = smem + 328;         // 2010
        float* red = smem + 2338;        // 128 x 10
        for (int i = tid; i < C_ * KW_; i += 256) wS[i] = W_conv[i];
        for (int i = tid; i < 128 + 2 * FW_; i += 256) {
            int t = t0 + i - FW_;
            ap[i] = (t >= 0 && t < T_) ? att_prev[(size_t)b * T_ + t] : 0.f;
        }
        __syncthreads();
        const int tl   = tid & 127;
        const int part = tid >> 7;
        const int k0 = part * 101;
        const int k1 = part ? KW_ : 101;
        float acc[C_];
        #pragma unroll
        for (int cc = 0; cc < C_; cc++) acc[cc] = 0.f;
        for (int k = k0; k < k1; k++) {
            float a = ap[tl + k];
            #pragma unroll
            for (int cc = 0; cc < C_; cc++) acc[cc] += a * wS[cc * KW_ + k];
        }
        if (part == 1) {
            #pragma unroll
            for (int cc = 0; cc < C_; cc++) red[tl * C_ + cc] = acc[cc];
        }
        __syncthreads();
        if (part == 0) {
            __half* dst = &g_conv_h[((size_t)b * T_ + t0 + tl) * 32];
            #pragma unroll
            for (int cc = 0; cc < C_; cc++)
                dst[cc] = __float2half_rn(acc[cc] + red[tl * C_ + cc]);
            #pragma unroll
            for (int cc = C_; cc < 32; cc++) dst[cc] = __float2half_rn(0.f);
        }
    } else if (bid < PREP_WENC) {
        // ---- bias: 64 rows per block ----
        const int li  = bid - PREP_BIAS;
        const int b   = li >> 3;
        const int grp = li & 7;
        float* qS = smem;
        qS[tid]       = query[b * D_ + tid];
        qS[tid + 256] = query[b * D_ + tid + 256];
        __syncthreads();
        const int warp = tid >> 5, lane = tid & 31;
        #pragma unroll
        for (int i = 0; i < 8; i++) {
            int r = grp * 64 + warp * 8 + i;
            float s = 0.f;
            const float* wp = W_dec + (size_t)r * D_;
            #pragma unroll
            for (int k = 0; k < 16; k++) s += wp[lane + k * 32] * qS[lane + k * 32];
            #pragma unroll
            for (int o = 16; o > 0; o >>= 1) s += __shfl_xor_sync(0xffffffffu, s, o);
            if (lane == 0) g_bias[b * D_ + r] = s + b_enc[r];
        }
    } else if (bid < PREP_WATT) {
        // ---- W_enc -> fp16 ----
        const int i = ((bid - PREP_WENC) * 256 + tid) * 4;
        float4 f = *reinterpret_cast<const float4*>(W_enc + i);
        Half4 o;
        o.h[0] = __floats2half2_rn(f.x, f.y);
        o.h[1] = __floats2half2_rn(f.z, f.w);
        *reinterpret_cast<Half4*>(g_wenc_h + i) = o;
    } else if (bid == PREP_WATT) {
        // ---- W_att pad ----
        #pragma unroll
        for (int j = 0; j < 64; j++) {
            int idx = tid + j * 256;
            int r = idx >> 5, cc = idx & 31;
            g_watt_h[idx] = (cc < C_) ? __float2half_rn(W_att[r * C_ + cc])
                                      : __float2half_rn(0.f);
        }
    } else {
        // ---- value -> fp16, 32B per thread ----
        const size_t i = ((size_t)(bid - PREP_CVT) * 256 + tid) * 8;
        float4 a = *reinterpret_cast<const float4*>(value + i);
        float4 b4 = *reinterpret_cast<const float4*>(value + i + 4);
        Half8 o;
        o.h[0] = __floats2half2_rn(a.x, a.y);
        o.h[1] = __floats2half2_rn(a.z, a.w);
        o.h[2] = __floats2half2_rn(b4.x, b4.y);
        o.h[3] = __floats2half2_rn(b4.z, b4.w);
        *reinterpret_cast<Half8*>(g_val_h + i) = o;
    }
}

// ---------------- kernel 3: pipelined FP16 GEMM + e epilogue ----------------
#define PITCH  80
#define A_BY   (128 * PITCH)             // 10240
#define Bb_BY  (256 * PITCH)             // 20480
#define ST_BY  (A_BY + Bb_BY)            // 30720
#define NSTAGE 6
#define DYN_SMEM (NSTAGE * ST_BY)        // 184320

__device__ __forceinline__ void stage_cp(const __half* __restrict__ srcA, int ldA,
                                         const __half* __restrict__ srcB, int ldB,
                                         uint32_t st, int tid) {
    {
        int r = tid >> 2, c4 = tid & 3;
        cp16(st + r * PITCH + c4 * 16, srcA + (size_t)r * ldA + c4 * 8);
    }
    #pragma unroll
    for (int i = 0; i < 2; i++) {
        int slot = tid + i * 512;
        int r = slot >> 2, c4 = slot & 3;
        cp16(st + A_BY + r * PITCH + c4 * 16, srcB + (size_t)r * ldB + c4 * 8);
    }
}

__global__ __launch_bounds__(512, 1)
void gemm_e_kernel(const float* __restrict__ w_g) {
    extern __shared__ char dynsmem[];
    const uint32_t sb = smem_u32(dynsmem);

    __shared__ float biasS[256];
    __shared__ float wgS[256];
    __shared__ float redS[128][4];

    const int tid  = threadIdx.x;
    const int lane = tid & 31;
    const int warp = tid >> 5;
    const int wm = warp & 3;
    const int wn = warp >> 2;
    const int q  = lane & 3;
    const int g  = lane >> 2;

    const int b  = blockIdx.z;
    const int t0 = blockIdx.x * 128;
    const int d0 = blockIdx.y * 256;
    const size_t tok0 = (size_t)b * T_ + t0;

    if (tid < 256) {
        biasS[tid] = g_bias[b * D_ + d0 + tid];
        wgS[tid]   = w_g[d0 + tid];
    }

    float c[2][8][4];
    #pragma unroll
    for (int mi = 0; mi < 2; mi++)
        #pragma unroll
        for (int ni = 0; ni < 8; ni++)
            #pragma unroll
            for (int e = 0; e < 4; e++) c[mi][ni][e] = 0.f;

    const __half* Ag = g_val_h + tok0 * D_;
    const __half* Bg = g_wenc_h + (size_t)d0 * D_;

    // prologue: stage tiles 0..4
    #pragma unroll
    for (int p = 0; p < 5; p++) {
        stage_cp(Ag + p * 32, D_, Bg + p * 32, D_, sb + p * ST_BY, tid);
        cp_commit();
    }

    const uint32_t aOff = (uint32_t)((wm * 32 + (lane & 15)) * PITCH + ((lane >> 4) << 4));
    const uint32_t bOff = (uint32_t)((wn * 64 + (lane & 7) + (((lane >> 4) & 1) << 3)) * PITCH
                                     + (((lane >> 3) & 1) << 4));

    for (int kt = 0; kt < 17; kt++) {
        cp_wait<4>();
        __syncthreads();

        const uint32_t stage = sb + (kt % NSTAGE) * ST_BY;
        const uint32_t aBase = stage + aOff;
        const uint32_t bBase = stage + A_BY + bOff;

        // ---- kk = 0 ----
        {
            unsigned af[2][4], bf[8][2];
            #pragma unroll
            for (int mi = 0; mi < 2; mi++)
                ldsm_x4(af[mi][0], af[mi][1], af[mi][2], af[mi][3],
                        aBase + mi * (16 * PITCH));
            #pragma unroll
            for (int p = 0; p < 4; p++)
                ldsm_x4(bf[2 * p][0], bf[2 * p][1], bf[2 * p + 1][0], bf[2 * p + 1][1],
                        bBase + p * (16 * PITCH));
            #pragma unroll
            for (int mi = 0; mi < 2; mi++)
                #pragma unroll
                for (int ni = 0; ni < 8; ni++)
                    mma16(c[mi][ni][0], c[mi][ni][1], c[mi][ni][2], c[mi][ni][3],
                          af[mi][0], af[mi][1], af[mi][2], af[mi][3],
                          bf[ni][0], bf[ni][1]);
        }

        // ---- stage tile kt+5 into drained stage (kt-1)%6 ----
        {
            const int j = kt + 5;
            if (j <= 16) {
                const uint32_t st = sb + (j % NSTAGE) * ST_BY;
                if (j < 16)
                    stage_cp(Ag + j * 32, D_, Bg + j * 32, D_, st, tid);
                else
                    stage_cp(g_conv_h + tok0 * 32, 32,
                             g_watt_h + (size_t)d0 * 32, 32, st, tid);
            }
            cp_commit();
        }

        // ---- kk = 1 ----
        {
            unsigned af[2][4], bf[8][2];
            #pragma unroll
            for (int mi = 0; mi < 2; mi++)
                ldsm_x4(af[mi][0], af[mi][1], af[mi][2], af[mi][3],
                        aBase + mi * (16 * PITCH) + 32);
            #pragma unroll
            for (int p = 0; p < 4; p++)
                ldsm_x4(bf[2 * p][0], bf[2 * p][1], bf[2 * p + 1][0], bf[2 * p + 1][1],
                        bBase + p * (16 * PITCH) + 32);
            #pragma unroll
            for (int mi = 0; mi < 2; mi++)
                #pragma unroll
                for (int ni = 0; ni < 8; ni++)
                    mma16(c[mi][ni][0], c[mi][ni][1], c[mi][ni][2], c[mi][ni][3],
                          af[mi][0], af[mi][1], af[mi][2], af[mi][3],
                          bf[ni][0], bf[ni][1]);
        }
    }

    // epilogue
    float rs[2][2];
    rs[0][0] = rs[0][1] = rs[1][0] = rs[1][1] = 0.f;
    #pragma unroll
    for (int mi = 0; mi < 2; mi++)
        #pragma unroll
        for (int ni = 0; ni < 8; ni++)
            #pragma unroll
            for (int e = 0; e < 4; e++) {
                int dl  = wn * 64 + ni * 8 + q * 2 + (e & 1);
                float x = c[mi][ni][e] + biasS[dl];
                rs[mi][e >> 1] += wgS[dl] * tanhf(x);
            }
    #pragma unroll
    for (int mi = 0; mi < 2; mi++)
        #pragma unroll
        for (int h = 0; h < 2; h++) {
            float v = rs[mi][h];
            v += __shfl_xor_sync(0xffffffffu, v, 1);
            v += __shfl_xor_sync(0xffffffffu, v, 2);
            if (q == 0) redS[wm * 32 + mi * 16 + h * 8 + g][wn] = v;
        }
    __syncthreads();
    if (tid < 128) {
        float ev = redS[tid][0] + redS[tid][1] + redS[tid][2] + redS[tid][3];
        g_epart[(tok0 + tid) * 2 + blockIdx.y] = ev;
    }
}

// ---------------- kernel 4: masked, sharpened softmax over T ----------------
__global__ __launch_bounds__(1024)
void softmax_kernel(const int* __restrict__ lens, float* __restrict__ out) {
    const int b   = blockIdx.x;
    const int len = lens[b];
    const int tid = threadIdx.x;
    __shared__ float sm[32];
    __shared__ float bc;

    float ev[4];
    float m = -1e30f;
    #pragma unroll
    for (int i = 0; i < 4; i++) {
        int t = tid + i * 1024;
        const float* p = &g_epart[((size_t)b * T_ + t) * 2];
        float e = p[0] + p[1];
        ev[i] = e;
        if (t < len) m = fmaxf(m, e);
    }
    #pragma unroll
    for (int o = 16; o > 0; o >>= 1) m = fmaxf(m, __shfl_xor_sync(0xffffffffu, m, o));
    if ((tid & 31) == 0) sm[tid >> 5] = m;
    __syncthreads();
    if (tid < 32) {
        float v = sm[tid];
        #pragma unroll
        for (int o = 16; o > 0; o >>= 1) v = fmaxf(v, __shfl_xor_sync(0xffffffffu, v, o));
        if (tid == 0) bc = v;
    }
    __syncthreads();
    const float M = bc;

    float s = 0.f;
    #pragma unroll
    for (int i = 0; i < 4; i++) {
        int t = tid + i * 1024;
        float w = (t < len) ? expf(2.0f * (ev[i] - M)) : 0.f;
        ev[i] = w;
        s += w;
    }
    #pragma unroll
    for (int o = 16; o > 0; o >>= 1) s += __shfl_xor_sync(0xffffffffu, s, o);
    __syncthreads();
    if ((tid & 31) == 0) sm[tid >> 5] = s;
    __syncthreads();
    if (tid < 32) {
        float v = sm[tid];
        #pragma unroll
        for (int o = 16; o > 0; o >>= 1) v += __shfl_xor_sync(0xffffffffu, v, o);
        if (tid == 0) bc = v;
    }
    __syncthreads();
    const float inv = 1.f / bc;
    #pragma unroll
    for (int i = 0; i < 4; i++) {
        int t = tid + i * 1024;
        out[B_ * D_ + (size_t)b * T_ + t] = ev[i] * inv;
    }
}

// ---------------- kernel 5: context partials (Half8 loads, 32 segs) ---------
__global__ __launch_bounds__(256)
void ctx_part_kernel(const float* __restrict__ wts) {
    const int seg = blockIdx.x, b = blockIdx.y;
    const int tid = threadIdx.x;
    const int t0  = seg * 128;
    __shared__ float wS[128];
    __shared__ float red[4][D_];
    if (tid < 128) wS[tid] = wts[(size_t)b * T_ + t0 + tid];
    __syncthreads();

    const int dg = tid & 63;         // 64 groups of 8 d
    const int tr = tid >> 6;         // 4 token rows in flight
    const int d0 = dg * 8;

    float acc[8];
    #pragma unroll
    for (int j = 0; j < 8; j++) acc[j] = 0.f;

    const __half* base = g_val_h + ((size_t)b * T_ + t0) * D_ + d0;
    for (int t = tr; t < 128; t += 4) {
        Half8 v = *reinterpret_cast<const Half8*>(base + (size_t)t * D_);
        float w = wS[t];
        #pragma unroll
        for (int j = 0; j < 4; j++) {
            float2 f = __half22float2(v.h[j]);
            acc[2 * j]     += f.x * w;
            acc[2 * j + 1] += f.y * w;
        }
    }
    #pragma unroll
    for (int j = 0; j < 8; j++) red[tr][d0 + j] = acc[j];
    __syncthreads();

    // 256 threads x 2 d each: sum 4 rows
    #pragma unroll
    for (int j = 0; j < 2; j++) {
        int d = tid * 2 + j;
        float s = red[0][d] + red[1][d] + red[2][d] + red[3][d];
        g_ctxp[((size_t)(b * 32 + seg)) * D_ + d] = s;
    }
}

// ---------------- kernel 6: context reduce ----------------------------------
__global__ __launch_bounds__(512)
void ctx_reduce_kernel(float* __restrict__ out) {
    const int b = blockIdx.x;
    const int d = threadIdx.x;
    float s = 0.f;
    #pragma unroll
    for (int seg = 0; seg < 32; seg++) s += g_ctxp[((size_t)(b * 32 + seg)) * D_ + d];
    out[b * D_ + d] = s;
}

// ---------------- launch -----------------------------------------------------
extern "C" void kernel_launch(void* const* d_in, const int* in_sizes, int n_in,
                              void* d_out, int out_size) {
    const float* value   = (const float*)d_in[0];
    const float* query   = (const float*)d_in[1];
    const int*   lens    = (const int*)  d_in[2];
    const float* attprev = (const float*)d_in[3];
    const float* W_enc   = (const float*)d_in[4];
    const float* b_enc   = (const float*)d_in[5];
    const float* W_dec   = (const float*)d_in[6];
    const float* W_att   = (const float*)d_in[7];
    const float* W_conv  = (const float*)d_in[8];
    const float* w_g     = (const float*)d_in[9];
    // d_in[10] = b_g: constant shift, cancels under softmax -> unused
    float* out = (float*)d_out;   // [0,8192) = context, [8192,73728) = att_weights

    cudaFuncSetAttribute(gemm_e_kernel,
                         cudaFuncAttributeMaxDynamicSharedMemorySize, DYN_SMEM);

    prep_kernel<<<PREP_GRID, 256>>>(value, W_enc, W_att, query, W_dec, b_enc,
                                    attprev, W_conv);
    gemm_e_kernel<<<dim3(T_ / 128, 2, B_), 512, DYN_SMEM>>>(w_g);
    softmax_kernel<<<B_, 1024>>>(lens, out);
    ctx_part_kernel<<<dim3(32, B_), 256>>>(out + B_ * D_);
    ctx_reduce_kernel<<<B_, 512>>>(out);
}

// round 13
// speedup vs baseline: 3.5546x; 1.0310x over previous
#include <cuda_runtime.h>
#include <cuda_fp16.h>
#include <cstdint>

#define B_  16
#define T_  4096
#define D_  512
#define C_  10
#define FW_ 100
#define KW_ 201   // 2*FW+1

// ---------------- scratch (device globals; no allocations allowed) ----------
__device__ float  g_bias[B_ * D_];            // b_enc[d] + (query @ W_dec.T)[b,d]
__device__ __half g_val_h[(size_t)B_ * T_ * D_];   // value in fp16 (64 MB)
__device__ __half g_wenc_h[D_ * D_];          // W_enc fp16 [d][k]
__device__ __half g_conv_h[(size_t)B_ * T_ * 32];  // [b*T+t][32]: 0..9 conv, rest 0
__device__ __half g_watt_h[D_ * 32];          // [d][32]: 0..9 W_att, rest 0
__device__ float  g_epart[B_ * T_ * 2];       // partial e per d-half
__device__ float  g_ctxp[B_ * 32 * D_];       // context partials per t-segment

// ---------------- helpers ---------------------------------------------------
__device__ __forceinline__ uint32_t smem_u32(const void* p) {
    uint32_t a;
    asm("{ .reg .u64 t; cvta.to.shared.u64 t, %1; cvt.u32.u64 %0, t; }" : "=r"(a) : "l"(p));
    return a;
}
__device__ __forceinline__ void cp16(uint32_t dst, const void* src) {
    asm volatile("cp.async.cg.shared.global [%0], [%1], 16;" :: "r"(dst), "l"(src));
}
__device__ __forceinline__ void cp_commit() {
    asm volatile("cp.async.commit_group;" ::: "memory");
}
template <int N>
__device__ __forceinline__ void cp_wait() {
    asm volatile("cp.async.wait_group %0;" :: "n"(N) : "memory");
}
__device__ __forceinline__ void ldsm_x4(unsigned& r0, unsigned& r1, unsigned& r2, unsigned& r3,
                                        uint32_t addr) {
    asm volatile("ldmatrix.sync.aligned.m8n8.x4.shared.b16 {%0,%1,%2,%3}, [%4];"
                 : "=r"(r0), "=r"(r1), "=r"(r2), "=r"(r3) : "r"(addr));
}
__device__ __forceinline__ void mma16(float& c0, float& c1, float& c2, float& c3,
                                      unsigned a0, unsigned a1, unsigned a2, unsigned a3,
                                      unsigned b0, unsigned b1) {
    asm volatile(
        "mma.sync.aligned.m16n8k16.row.col.f32.f16.f16.f32 "
        "{%0,%1,%2,%3}, {%4,%5,%6,%7}, {%8,%9}, {%0,%1,%2,%3};"
        : "+f"(c0), "+f"(c1), "+f"(c2), "+f"(c3)
        : "r"(a0), "r"(a1), "r"(a2), "r"(a3), "r"(b0), "r"(b1));
}

struct alignas(16) Half8 { __half2 h[4]; };
struct alignas(8)  Half4 { __half2 h[2]; };

// ---------------- merged prep kernel ----------------------------------------
#define PREP_CONV   0
#define PREP_BIAS   512
#define PREP_WENC   640
#define PREP_WATT   896
#define PREP_CVT    897
#define PREP_GRID   (PREP_CVT + 16384)

__global__ __launch_bounds__(256)
void prep_kernel(const float* __restrict__ value, const float* __restrict__ W_enc,
                 const float* __restrict__ W_att, const float* __restrict__ query,
                 const float* __restrict__ W_dec, const float* __restrict__ b_enc,
                 const float* __restrict__ att_prev, const float* __restrict__ W_conv) {
    __shared__ float smem[3664];    // conv: ap[328] + wS[2010] + red[1280]
    const int bid = blockIdx.x;
    const int tid = threadIdx.x;

    if (bid < PREP_BIAS) {
        // ---- conv: 128 tokens per block, 2-way tap split ----
        const int b  = bid >> 5;
        const int t0 = (bid & 31) * 128;
        float* ap  = smem;               // 328
        float* wS  = smem + 328;         // 2010
        float* red = smem + 2338;        // 128 x 10
        for (int i = tid; i < C_ * KW_; i += 256) wS[i] = W_conv[i];
        for (int i = tid; i < 128 + 2 * FW_; i += 256) {
            int t = t0 + i - FW_;
            ap[i] = (t >= 0 && t < T_) ? att_prev[(size_t)b * T_ + t] : 0.f;
        }
        __syncthreads();
        const int tl   = tid & 127;
        const int part = tid >> 7;
        const int k0 = part * 101;
        const int k1 = part ? KW_ : 101;
        float acc[C_];
        #pragma unroll
        for (int cc = 0; cc < C_; cc++) acc[cc] = 0.f;
        for (int k = k0; k < k1; k++) {
            float a = ap[tl + k];
            #pragma unroll
            for (int cc = 0; cc < C_; cc++) acc[cc] += a * wS[cc * KW_ + k];
        }
        if (part == 1) {
            #pragma unroll
            for (int cc = 0; cc < C_; cc++) red[tl * C_ + cc] = acc[cc];
        }
        __syncthreads();
        if (part == 0) {
            __half* dst = &g_conv_h[((size_t)b * T_ + t0 + tl) * 32];
            #pragma unroll
            for (int cc = 0; cc < C_; cc++)
                dst[cc] = __float2half_rn(acc[cc] + red[tl * C_ + cc]);
            #pragma unroll
            for (int cc = C_; cc < 32; cc++) dst[cc] = __float2half_rn(0.f);
        }
    } else if (bid < PREP_WENC) {
        // ---- bias: 64 rows per block ----
        const int li  = bid - PREP_BIAS;
        const int b   = li >> 3;
        const int grp = li & 7;
        float* qS = smem;
        qS[tid]       = query[b * D_ + tid];
        qS[tid + 256] = query[b * D_ + tid + 256];
        __syncthreads();
        const int warp = tid >> 5, lane = tid & 31;
        #pragma unroll
        for (int i = 0; i < 8; i++) {
            int r = grp * 64 + warp * 8 + i;
            float s = 0.f;
            const float* wp = W_dec + (size_t)r * D_;
            #pragma unroll
            for (int k = 0; k < 16; k++) s += wp[lane + k * 32] * qS[lane + k * 32];
            #pragma unroll
            for (int o = 16; o > 0; o >>= 1) s += __shfl_xor_sync(0xffffffffu, s, o);
            if (lane == 0) g_bias[b * D_ + r] = s + b_enc[r];
        }
    } else if (bid < PREP_WATT) {
        // ---- W_enc -> fp16 ----
        const int i = ((bid - PREP_WENC) * 256 + tid) * 4;
        float4 f = *reinterpret_cast<const float4*>(W_enc + i);
        Half4 o;
        o.h[0] = __floats2half2_rn(f.x, f.y);
        o.h[1] = __floats2half2_rn(f.z, f.w);
        *reinterpret_cast<Half4*>(g_wenc_h + i) = o;
    } else if (bid == PREP_WATT) {
        // ---- W_att pad ----
        #pragma unroll
        for (int j = 0; j < 64; j++) {
            int idx = tid + j * 256;
            int r = idx >> 5, cc = idx & 31;
            g_watt_h[idx] = (cc < C_) ? __float2half_rn(W_att[r * C_ + cc])
                                      : __float2half_rn(0.f);
        }
    } else {
        // ---- value -> fp16, 32B per thread ----
        const size_t i = ((size_t)(bid - PREP_CVT) * 256 + tid) * 8;
        float4 a = *reinterpret_cast<const float4*>(value + i);
        float4 b4 = *reinterpret_cast<const float4*>(value + i + 4);
        Half8 o;
        o.h[0] = __floats2half2_rn(a.x, a.y);
        o.h[1] = __floats2half2_rn(a.z, a.w);
        o.h[2] = __floats2half2_rn(b4.x, b4.y);
        o.h[3] = __floats2half2_rn(b4.z, b4.w);
        *reinterpret_cast<Half8*>(g_val_h + i) = o;
    }
}

// ---------------- kernel 3: pipelined FP16 GEMM + e epilogue ----------------
#define PITCH  80
#define A_BY   (128 * PITCH)             // 10240
#define Bb_BY  (256 * PITCH)             // 20480
#define ST_BY  (A_BY + Bb_BY)            // 30720
#define NSTAGE 6
#define DYN_SMEM (NSTAGE * ST_BY)        // 184320

__device__ __forceinline__ void stage_cp(const __half* __restrict__ srcA, int ldA,
                                         const __half* __restrict__ srcB, int ldB,
                                         uint32_t st, int tid) {
    {
        int r = tid >> 2, c4 = tid & 3;
        cp16(st + r * PITCH + c4 * 16, srcA + (size_t)r * ldA + c4 * 8);
    }
    #pragma unroll
    for (int i = 0; i < 2; i++) {
        int slot = tid + i * 512;
        int r = slot >> 2, c4 = slot & 3;
        cp16(st + A_BY + r * PITCH + c4 * 16, srcB + (size_t)r * ldB + c4 * 8);
    }
}

__global__ __launch_bounds__(512, 1)
void gemm_e_kernel(const float* __restrict__ w_g) {
    extern __shared__ char dynsmem[];
    const uint32_t sb = smem_u32(dynsmem);

    __shared__ float biasS[256];
    __shared__ float wgS[256];
    __shared__ float redS[128][4];

    const int tid  = threadIdx.x;
    const int lane = tid & 31;
    const int warp = tid >> 5;
    const int wm = warp & 3;
    const int wn = warp >> 2;
    const int q  = lane & 3;
    const int g  = lane >> 2;

    const int b  = blockIdx.z;
    const int t0 = blockIdx.x * 128;
    const int d0 = blockIdx.y * 256;
    const size_t tok0 = (size_t)b * T_ + t0;

    if (tid < 256) {
        biasS[tid] = g_bias[b * D_ + d0 + tid];
        wgS[tid]   = w_g[d0 + tid];
    }

    float c[2][8][4];
    #pragma unroll
    for (int mi = 0; mi < 2; mi++)
        #pragma unroll
        for (int ni = 0; ni < 8; ni++)
            #pragma unroll
            for (int e = 0; e < 4; e++) c[mi][ni][e] = 0.f;

    const __half* Ag = g_val_h + tok0 * D_;
    const __half* Bg = g_wenc_h + (size_t)d0 * D_;

    // prologue: stage tiles 0..4
    #pragma unroll
    for (int p = 0; p < 5; p++) {
        stage_cp(Ag + p * 32, D_, Bg + p * 32, D_, sb + p * ST_BY, tid);
        cp_commit();
    }

    const uint32_t aOff = (uint32_t)((wm * 32 + (lane & 15)) * PITCH + ((lane >> 4) << 4));
    const uint32_t bOff = (uint32_t)((wn * 64 + (lane & 7) + (((lane >> 4) & 1) << 3)) * PITCH
                                     + (((lane >> 3) & 1) << 4));

    for (int kt = 0; kt < 17; kt++) {
        cp_wait<4>();
        __syncthreads();

        const uint32_t stage = sb + (kt % NSTAGE) * ST_BY;
        const uint32_t aBase = stage + aOff;
        const uint32_t bBase = stage + A_BY + bOff;

        // ---- kk = 0 ----
        {
            unsigned af[2][4], bf[8][2];
            #pragma unroll
            for (int mi = 0; mi < 2; mi++)
                ldsm_x4(af[mi][0], af[mi][1], af[mi][2], af[mi][3],
                        aBase + mi * (16 * PITCH));
            #pragma unroll
            for (int p = 0; p < 4; p++)
                ldsm_x4(bf[2 * p][0], bf[2 * p][1], bf[2 * p + 1][0], bf[2 * p + 1][1],
                        bBase + p * (16 * PITCH));
            #pragma unroll
            for (int mi = 0; mi < 2; mi++)
                #pragma unroll
                for (int ni = 0; ni < 8; ni++)
                    mma16(c[mi][ni][0], c[mi][ni][1], c[mi][ni][2], c[mi][ni][3],
                          af[mi][0], af[mi][1], af[mi][2], af[mi][3],
                          bf[ni][0], bf[ni][1]);
        }

        // ---- stage tile kt+5 into drained stage ----
        {
            const int j = kt + 5;
            if (j <= 16) {
                const uint32_t st = sb + (j % NSTAGE) * ST_BY;
                if (j < 16)
                    stage_cp(Ag + j * 32, D_, Bg + j * 32, D_, st, tid);
                else
                    stage_cp(g_conv_h + tok0 * 32, 32,
                             g_watt_h + (size_t)d0 * 32, 32, st, tid);
            }
            cp_commit();
        }

        // ---- kk = 1 ----
        {
            unsigned af[2][4], bf[8][2];
            #pragma unroll
            for (int mi = 0; mi < 2; mi++)
                ldsm_x4(af[mi][0], af[mi][1], af[mi][2], af[mi][3],
                        aBase + mi * (16 * PITCH) + 32);
            #pragma unroll
            for (int p = 0; p < 4; p++)
                ldsm_x4(bf[2 * p][0], bf[2 * p][1], bf[2 * p + 1][0], bf[2 * p + 1][1],
                        bBase + p * (16 * PITCH) + 32);
            #pragma unroll
            for (int mi = 0; mi < 2; mi++)
                #pragma unroll
                for (int ni = 0; ni < 8; ni++)
                    mma16(c[mi][ni][0], c[mi][ni][1], c[mi][ni][2], c[mi][ni][3],
                          af[mi][0], af[mi][1], af[mi][2], af[mi][3],
                          bf[ni][0], bf[ni][1]);
        }
    }

    // epilogue
    float rs[2][2];
    rs[0][0] = rs[0][1] = rs[1][0] = rs[1][1] = 0.f;
    #pragma unroll
    for (int mi = 0; mi < 2; mi++)
        #pragma unroll
        for (int ni = 0; ni < 8; ni++)
            #pragma unroll
            for (int e = 0; e < 4; e++) {
                int dl  = wn * 64 + ni * 8 + q * 2 + (e & 1);
                float x = c[mi][ni][e] + biasS[dl];
                rs[mi][e >> 1] += wgS[dl] * tanhf(x);
            }
    #pragma unroll
    for (int mi = 0; mi < 2; mi++)
        #pragma unroll
        for (int h = 0; h < 2; h++) {
            float v = rs[mi][h];
            v += __shfl_xor_sync(0xffffffffu, v, 1);
            v += __shfl_xor_sync(0xffffffffu, v, 2);
            if (q == 0) redS[wm * 32 + mi * 16 + h * 8 + g][wn] = v;
        }
    __syncthreads();
    if (tid < 128) {
        float ev = redS[tid][0] + redS[tid][1] + redS[tid][2] + redS[tid][3];
        g_epart[(tok0 + tid) * 2 + blockIdx.y] = ev;
    }
}

// ---------------- kernel 4: masked, sharpened softmax over T ----------------
__global__ __launch_bounds__(1024)
void softmax_kernel(const int* __restrict__ lens, float* __restrict__ out) {
    const int b   = blockIdx.x;
    const int len = lens[b];
    const int tid = threadIdx.x;
    __shared__ float sm[32];
    __shared__ float bc;

    float ev[4];
    float m = -1e30f;
    #pragma unroll
    for (int i = 0; i < 4; i++) {
        int t = tid + i * 1024;
        const float* p = &g_epart[((size_t)b * T_ + t) * 2];
        float e = p[0] + p[1];
        ev[i] = e;
        if (t < len) m = fmaxf(m, e);
    }
    #pragma unroll
    for (int o = 16; o > 0; o >>= 1) m = fmaxf(m, __shfl_xor_sync(0xffffffffu, m, o));
    if ((tid & 31) == 0) sm[tid >> 5] = m;
    __syncthreads();
    if (tid < 32) {
        float v = sm[tid];
        #pragma unroll
        for (int o = 16; o > 0; o >>= 1) v = fmaxf(v, __shfl_xor_sync(0xffffffffu, v, o));
        if (tid == 0) bc = v;
    }
    __syncthreads();
    const float M = bc;

    float s = 0.f;
    #pragma unroll
    for (int i = 0; i < 4; i++) {
        int t = tid + i * 1024;
        float w = (t < len) ? expf(2.0f * (ev[i] - M)) : 0.f;
        ev[i] = w;
        s += w;
    }
    #pragma unroll
    for (int o = 16; o > 0; o >>= 1) s += __shfl_xor_sync(0xffffffffu, s, o);
    __syncthreads();
    if ((tid & 31) == 0) sm[tid >> 5] = s;
    __syncthreads();
    if (tid < 32) {
        float v = sm[tid];
        #pragma unroll
        for (int o = 16; o > 0; o >>= 1) v += __shfl_xor_sync(0xffffffffu, v, o);
        if (tid == 0) bc = v;
    }
    __syncthreads();
    const float inv = 1.f / bc;
    #pragma unroll
    for (int i = 0; i < 4; i++) {
        int t = tid + i * 1024;
        out[B_ * D_ + (size_t)b * T_ + t] = ev[i] * inv;
    }
}

// ---------------- kernel 5: context partials (4-way unrolled loads) ---------
__global__ __launch_bounds__(256)
void ctx_part_kernel(const float* __restrict__ wts) {
    const int seg = blockIdx.x, b = blockIdx.y;
    const int tid = threadIdx.x;
    const int t0  = seg * 128;
    __shared__ float wS[128];
    __shared__ float red[4][D_];
    if (tid < 128) wS[tid] = wts[(size_t)b * T_ + t0 + tid];
    __syncthreads();

    const int dg = tid & 63;         // 64 groups of 8 d
    const int tr = tid >> 6;         // 4 token rows in flight
    const int d0 = dg * 8;

    float acc[8];
    #pragma unroll
    for (int j = 0; j < 8; j++) acc[j] = 0.f;

    const __half* base = g_val_h + ((size_t)b * T_ + t0) * D_ + d0;
    // 8 iterations; 4 independent Half8 loads per iteration (MLP=4)
    #pragma unroll 2
    for (int t = tr; t < 128; t += 16) {
        Half8 v0 = *reinterpret_cast<const Half8*>(base + (size_t)(t     ) * D_);
        Half8 v1 = *reinterpret_cast<const Half8*>(base + (size_t)(t +  4) * D_);
        Half8 v2 = *reinterpret_cast<const Half8*>(base + (size_t)(t +  8) * D_);
        Half8 v3 = *reinterpret_cast<const Half8*>(base + (size_t)(t + 12) * D_);
        float w0 = wS[t], w1 = wS[t + 4], w2 = wS[t + 8], w3 = wS[t + 12];
        #pragma unroll
        for (int j = 0; j < 4; j++) {
            float2 f0 = __half22float2(v0.h[j]);
            float2 f1 = __half22float2(v1.h[j]);
            float2 f2 = __half22float2(v2.h[j]);
            float2 f3 = __half22float2(v3.h[j]);
            acc[2 * j]     += f0.x * w0 + f1.x * w1 + f2.x * w2 + f3.x * w3;
            acc[2 * j + 1] += f0.y * w0 + f1.y * w1 + f2.y * w2 + f3.y * w3;
        }
    }
    #pragma unroll
    for (int j = 0; j < 8; j++) red[tr][d0 + j] = acc[j];
    __syncthreads();

    // 256 threads x 2 d each: sum 4 rows
    #pragma unroll
    for (int j = 0; j < 2; j++) {
        int d = tid * 2 + j;
        float s = red[0][d] + red[1][d] + red[2][d] + red[3][d];
        g_ctxp[((size_t)(b * 32 + seg)) * D_ + d] = s;
    }
}

// ---------------- kernel 6: context reduce ----------------------------------
__global__ __launch_bounds__(512)
void ctx_reduce_kernel(float* __restrict__ out) {
    const int b = blockIdx.x;
    const int d = threadIdx.x;
    float s = 0.f;
    #pragma unroll
    for (int seg = 0; seg < 32; seg++) s += g_ctxp[((size_t)(b * 32 + seg)) * D_ + d];
    out[b * D_ + d] = s;
}

// ---------------- launch -----------------------------------------------------
extern "C" void kernel_launch(void* const* d_in, const int* in_sizes, int n_in,
                              void* d_out, int out_size) {
    const float* value   = (const float*)d_in[0];
    const float* query   = (const float*)d_in[1];
    const int*   lens    = (const int*)  d_in[2];
    const float* attprev = (const float*)d_in[3];
    const float* W_enc   = (const float*)d_in[4];
    const float* b_enc   = (const float*)d_in[5];
    const float* W_dec   = (const float*)d_in[6];
    const float* W_att   = (const float*)d_in[7];
    const float* W_conv  = (const float*)d_in[8];
    const float* w_g     = (const float*)d_in[9];
    // d_in[10] = b_g: constant shift, cancels under softmax -> unused
    float* out = (float*)d_out;   // [0,8192) = context, [8192,73728) = att_weights

    cudaFuncSetAttribute(gemm_e_kernel,
                         cudaFuncAttributeMaxDynamicSharedMemorySize, DYN_SMEM);

    prep_kernel<<<PREP_GRID, 256>>>(value, W_enc, W_att, query, W_dec, b_enc,
                                    attprev, W_conv);
    gemm_e_kernel<<<dim3(T_ / 128, 2, B_), 512, DYN_SMEM>>>(w_g);
    softmax_kernel<<<B_, 1024>>>(lens, out);
    ctx_part_kernel<<<dim3(32, B_), 256>>>(out + B_ * D_);
    ctx_reduce_kernel<<<B_, 512>>>(out);
}